// round 1
// baseline (speedup 1.0000x reference)
#include <cuda_runtime.h>
#include <math.h>

#define BATCH   8192
#define FPDIM   4860
#define EDIM    256
#define HDIM    256
#define VDIM    42
#define TSTEPS  128

// ---------------------------------------------------------------------------
// Static device scratch (no allocations allowed in kernel_launch)
// ---------------------------------------------------------------------------
__device__ float g_act0[(size_t)BATCH * 2048];                    // 64 MB
__device__ float g_act1[(size_t)BATCH * 1024];                    // 32 MB
__device__ float g_giA [(size_t)BATCH * 1536];                    // 50 MB  (gi0 | gh1)
__device__ float g_gh0 [(size_t)BATCH * 768];                     // 25 MB
__device__ float g_gi1 [(size_t)BATCH * 768];                     // 25 MB
__device__ float g_h0  [(size_t)BATCH * HDIM];                    // 8 MB
__device__ float g_hist[(size_t)(TSTEPS + 1) * BATCH * HDIM];     // 1.08 GB (slot s = h1_{s-1})
__device__ float g_wcat[1536 * HDIM];                             // [wih0 ; whh1]
__device__ float g_bcat[1536];                                    // [bih0 ; bhh1]

// ---------------------------------------------------------------------------
// SGEMM:  C[M,N] = A[M,K] @ W[N,K]^T + bias[N], optional ReLU
// BM=BN=128, BK=16, 8x8 microtile, 256 threads. K must be %4==0 (true here).
// Full M/N tiles assumed (all M,N here are multiples of 128).
// ---------------------------------------------------------------------------
template<bool RELU>
__global__ void __launch_bounds__(256, 2)
sgemm_nt(const float* __restrict__ A, int lda,
         const float* __restrict__ W,              // N x K, row-major
         const float* __restrict__ bias,
         float* __restrict__ C, int ldc,
         int M, int N, int K)
{
    const int BM = 128, BN = 128, BK = 16;
    __shared__ float As[BK][BM];
    __shared__ float Ws[BK][BN];

    const int tid = threadIdx.x;
    const int bm  = blockIdx.y * BM;
    const int bn  = blockIdx.x * BN;
    const int tx  = tid & 15;     // N direction (8 cols each)
    const int ty  = tid >> 4;     // M direction (8 rows each)

    const int lrow = tid >> 2;    // 0..63
    const int lc4  = tid & 3;     // float4 column index within BK

    float acc[8][8];
    #pragma unroll
    for (int i = 0; i < 8; i++)
        #pragma unroll
        for (int j = 0; j < 8; j++) acc[i][j] = 0.f;

    for (int k0 = 0; k0 < K; k0 += BK) {
        const int kcol = k0 + lc4 * 4;
        const bool kin = (kcol < K);
        #pragma unroll
        for (int r = 0; r < 2; r++) {
            const int row = lrow + r * 64;
            float4 va = make_float4(0.f, 0.f, 0.f, 0.f);
            float4 vw = make_float4(0.f, 0.f, 0.f, 0.f);
            if (kin) {
                va = *(const float4*)&A[(size_t)(bm + row) * lda + kcol];
                vw = *(const float4*)&W[(size_t)(bn + row) * K   + kcol];
            }
            As[lc4 * 4 + 0][row] = va.x; As[lc4 * 4 + 1][row] = va.y;
            As[lc4 * 4 + 2][row] = va.z; As[lc4 * 4 + 3][row] = va.w;
            Ws[lc4 * 4 + 0][row] = vw.x; Ws[lc4 * 4 + 1][row] = vw.y;
            Ws[lc4 * 4 + 2][row] = vw.z; Ws[lc4 * 4 + 3][row] = vw.w;
        }
        __syncthreads();

        #pragma unroll
        for (int kk = 0; kk < BK; kk++) {
            float a[8], b[8];
            *(float4*)&a[0] = *(const float4*)&As[kk][ty * 8];
            *(float4*)&a[4] = *(const float4*)&As[kk][ty * 8 + 4];
            *(float4*)&b[0] = *(const float4*)&Ws[kk][tx * 8];
            *(float4*)&b[4] = *(const float4*)&Ws[kk][tx * 8 + 4];
            #pragma unroll
            for (int i = 0; i < 8; i++)
                #pragma unroll
                for (int j = 0; j < 8; j++)
                    acc[i][j] = fmaf(a[i], b[j], acc[i][j]);
        }
        __syncthreads();
    }

    #pragma unroll
    for (int i = 0; i < 8; i++) {
        const int m = bm + ty * 8 + i;
        #pragma unroll
        for (int j = 0; j < 8; j += 4) {
            const int n = bn + tx * 8 + j;
            float4 o;
            o.x = acc[i][j + 0] + bias[n + 0];
            o.y = acc[i][j + 1] + bias[n + 1];
            o.z = acc[i][j + 2] + bias[n + 2];
            o.w = acc[i][j + 3] + bias[n + 3];
            if (RELU) {
                o.x = fmaxf(o.x, 0.f); o.y = fmaxf(o.y, 0.f);
                o.z = fmaxf(o.z, 0.f); o.w = fmaxf(o.w, 0.f);
            }
            *(float4*)&C[(size_t)m * ldc + n] = o;
        }
    }
}

// ---------------------------------------------------------------------------
// GRU gate elementwise:  h' = (1-z)*n + z*h
//   r = sig(gi_r + gh_r), z = sig(gi_z + gh_z), n = tanh(gi_n + r*gh_n)
// gi rows stride ldi, gh rows stride ldh; hprev/hnew contiguous B x H.
// ---------------------------------------------------------------------------
__device__ __forceinline__ float sigmoidf_(float x) { return 1.f / (1.f + expf(-x)); }

__global__ void gru_gates_kernel(const float* __restrict__ gi, int ldi,
                                 const float* __restrict__ gh, int ldh,
                                 const float* __restrict__ hprev,
                                 float* __restrict__ hnew)
{
    const int idx = blockIdx.x * blockDim.x + threadIdx.x;
    if (idx >= BATCH * HDIM) return;
    const int b = idx / HDIM;
    const int i = idx % HDIM;
    const float* gir = gi + (size_t)b * ldi;
    const float* ghr = gh + (size_t)b * ldh;
    const float r = sigmoidf_(gir[i]            + ghr[i]);
    const float z = sigmoidf_(gir[HDIM + i]     + ghr[HDIM + i]);
    const float n = tanhf   (gir[2 * HDIM + i]  + r * ghr[2 * HDIM + i]);
    hnew[idx] = (1.f - z) * n + z * hprev[idx];
}

// ---------------------------------------------------------------------------
// Prep: concat [wih0 ; whh1] and [bih0 ; bhh1]
// ---------------------------------------------------------------------------
__global__ void prep_wcat_kernel(const float* __restrict__ wih0,
                                 const float* __restrict__ whh1,
                                 const float* __restrict__ bih0,
                                 const float* __restrict__ bhh1)
{
    const int idx = blockIdx.x * blockDim.x + threadIdx.x;
    const int half = 768 * HDIM;
    if (idx < half)            g_wcat[idx] = wih0[idx];
    else if (idx < 2 * half)   g_wcat[idx] = whh1[idx - half];
    if (idx < 768)             g_bcat[idx] = bih0[idx];
    else if (idx < 1536)       g_bcat[idx] = bhh1[idx - 768];
}

__global__ void zero_kernel(float* __restrict__ p, int n)
{
    const int idx = blockIdx.x * blockDim.x + threadIdx.x;
    if (idx < n) p[idx] = 0.f;
}

// ---------------------------------------------------------------------------
// Fused FC + ReLU + softmax over V=42, one warp per (b, t) row.
// out[b][t][v] = softmax_v( relu( h1_t[b] @ wfc^T + bfc ) )
// ---------------------------------------------------------------------------
__global__ void __launch_bounds__(256)
fc_softmax_kernel(const float* __restrict__ hist,
                  const float* __restrict__ wfc,
                  const float* __restrict__ bfc,
                  float* __restrict__ out)
{
    const int gwarp = (blockIdx.x * blockDim.x + threadIdx.x) >> 5;
    const int lane  = threadIdx.x & 31;
    const int wl    = threadIdx.x >> 5;
    if (gwarp >= BATCH * TSTEPS) return;
    const int b = gwarp / TSTEPS;
    const int t = gwarp % TSTEPS;

    __shared__ float hs[8][HDIM];
    const float* h = hist + ((size_t)(t + 1) * BATCH + b) * HDIM;
    #pragma unroll
    for (int k = 0; k < HDIM / 32; k++) hs[wl][lane + k * 32] = h[lane + k * 32];
    __syncwarp();

    const float* hrow = hs[wl];
    const bool has2 = (lane < VDIM - 32);   // lanes 0..9 also handle o = lane+32

    float v0 = bfc[lane];
    {
        const float4* w4 = (const float4*)&wfc[(size_t)lane * HDIM];
        float acc = 0.f;
        #pragma unroll 8
        for (int k = 0; k < HDIM / 4; k++) {
            const float4 wv = w4[k];
            const float4 hv = *(const float4*)&hrow[k * 4];
            acc += wv.x * hv.x + wv.y * hv.y + wv.z * hv.z + wv.w * hv.w;
        }
        v0 += acc;
    }
    float v1 = -1e30f;
    if (has2) {
        v1 = bfc[lane + 32];
        const float4* w4 = (const float4*)&wfc[(size_t)(lane + 32) * HDIM];
        float acc = 0.f;
        #pragma unroll 8
        for (int k = 0; k < HDIM / 4; k++) {
            const float4 wv = w4[k];
            const float4 hv = *(const float4*)&hrow[k * 4];
            acc += wv.x * hv.x + wv.y * hv.y + wv.z * hv.z + wv.w * hv.w;
        }
        v1 += acc;
    }

    v0 = fmaxf(v0, 0.f);
    const float lv1 = has2 ? fmaxf(v1, 0.f) : -1e30f;

    float m = fmaxf(v0, lv1);
    #pragma unroll
    for (int off = 16; off; off >>= 1) m = fmaxf(m, __shfl_xor_sync(0xffffffffu, m, off));

    const float e0 = expf(v0 - m);
    const float e1 = has2 ? expf(lv1 - m) : 0.f;
    float s = e0 + e1;
    #pragma unroll
    for (int off = 16; off; off >>= 1) s += __shfl_xor_sync(0xffffffffu, s, off);

    const float inv = 1.f / s;
    float* o = out + (size_t)gwarp * VDIM;
    o[lane] = e0 * inv;
    if (has2) o[lane + 32] = e1 * inv;
}

// ---------------------------------------------------------------------------
// Launch
// ---------------------------------------------------------------------------
extern "C" void kernel_launch(void* const* d_in, const int* in_sizes, int n_in,
                              void* d_out, int out_size)
{
    const float* x    = (const float*)d_in[0];
    const float* w1   = (const float*)d_in[1];
    const float* b1   = (const float*)d_in[2];
    const float* w2   = (const float*)d_in[3];
    const float* b2   = (const float*)d_in[4];
    const float* w3   = (const float*)d_in[5];
    const float* b3   = (const float*)d_in[6];
    const float* w4   = (const float*)d_in[7];
    const float* b4   = (const float*)d_in[8];
    const float* wih0 = (const float*)d_in[9];
    const float* whh0 = (const float*)d_in[10];
    const float* bih0 = (const float*)d_in[11];
    const float* bhh0 = (const float*)d_in[12];
    const float* wih1 = (const float*)d_in[13];
    const float* whh1 = (const float*)d_in[14];
    const float* bih1 = (const float*)d_in[15];
    const float* bhh1 = (const float*)d_in[16];
    const float* wfc  = (const float*)d_in[17];
    const float* bfc  = (const float*)d_in[18];
    float* out = (float*)d_out;

    float *act0, *act1, *giA, *gh0, *gi1, *h0, *hist, *wcat, *bcat;
    cudaGetSymbolAddress((void**)&act0, g_act0);
    cudaGetSymbolAddress((void**)&act1, g_act1);
    cudaGetSymbolAddress((void**)&giA,  g_giA);
    cudaGetSymbolAddress((void**)&gh0,  g_gh0);
    cudaGetSymbolAddress((void**)&gi1,  g_gi1);
    cudaGetSymbolAddress((void**)&h0,   g_h0);
    cudaGetSymbolAddress((void**)&hist, g_hist);
    cudaGetSymbolAddress((void**)&wcat, g_wcat);
    cudaGetSymbolAddress((void**)&bcat, g_bcat);

    const int BH = BATCH * HDIM;

    // init: h0 = 0, hist slot 0 (= h1_{-1}) = 0, weight concat
    zero_kernel<<<(BH + 255) / 256, 256>>>(h0, BH);
    zero_kernel<<<(BH + 255) / 256, 256>>>(hist, BH);
    prep_wcat_kernel<<<(1536 * HDIM + 255) / 256, 256>>>(wih0, whh1, bih0, bhh1);

    // ---- encoder MLP ----
    sgemm_nt<true><<<dim3(2048 / 128, BATCH / 128), 256>>>(x,    FPDIM, w1, b1, act0, 2048, BATCH, 2048, FPDIM);
    sgemm_nt<true><<<dim3(1024 / 128, BATCH / 128), 256>>>(act0, 2048,  w2, b2, act1, 1024, BATCH, 1024, 2048);
    sgemm_nt<true><<<dim3(512  / 128, BATCH / 128), 256>>>(act1, 1024,  w3, b3, act0, 512,  BATCH, 512,  1024);
    sgemm_nt<true><<<dim3(256  / 128, BATCH / 128), 256>>>(act0, 512,   w4, b4, act1, 256,  BATCH, 256,  512);
    const float* e = act1;   // (B, E)

    // ---- GRU over T steps ----
    const dim3 g768 (768  / 128, BATCH / 128);
    const dim3 g1536(1536 / 128, BATCH / 128);
    const int gatesBlocks = (BH + 255) / 256;

    for (int t = 0; t < TSTEPS; t++) {
        const float* h1prev = hist + (size_t)t * BH;        // h1_{t-1}
        float*       h1new  = hist + (size_t)(t + 1) * BH;  // h1_t

        if (t == 0) {
            // gi0 = e @ wih0^T + bih0 ; gh1 = 0 @ whh1^T + bhh1 (zeros slot)
            sgemm_nt<false><<<g768, 256>>>(e,       EDIM, wih0, bih0, giA,       1536, BATCH, 768, EDIM);
            sgemm_nt<false><<<g768, 256>>>(h1prev,  HDIM, whh1, bhh1, giA + 768, 1536, BATCH, 768, HDIM);
        } else {
            // [gi0 | gh1] = h1_{t-1} @ [wih0 ; whh1]^T + [bih0 ; bhh1]
            sgemm_nt<false><<<g1536, 256>>>(h1prev, HDIM, wcat, bcat, giA, 1536, BATCH, 1536, HDIM);
        }
        // gh0 = h0_{t-1} @ whh0^T + bhh0   (h0 zero at t=0 -> bias only, correct)
        sgemm_nt<false><<<g768, 256>>>(h0, HDIM, whh0, bhh0, gh0, 768, BATCH, 768, HDIM);
        // h0_t
        gru_gates_kernel<<<gatesBlocks, 256>>>(giA, 1536, gh0, 768, h0, h0);
        // gi1 = h0_t @ wih1^T + bih1
        sgemm_nt<false><<<g768, 256>>>(h0, HDIM, wih1, bih1, gi1, 768, BATCH, 768, HDIM);
        // h1_t  (gh part = giA cols [768,1536))
        gru_gates_kernel<<<gatesBlocks, 256>>>(gi1, 768, giA + 768, 1536, h1prev, h1new);
    }

    // ---- fused FC + ReLU + softmax over all (b, t) ----
    const long long totalWarps = (long long)BATCH * TSTEPS;
    const int fcBlocks = (int)((totalWarps * 32 + 255) / 256);
    fc_softmax_kernel<<<fcBlocks, 256>>>(hist, wfc, bfc, out);
}

// round 2
// speedup vs baseline: 2.1812x; 2.1812x over previous
#include <cuda_runtime.h>
#include <math.h>
#include <stdint.h>

#define BATCH   8192
#define FPDIM   4860
#define EDIM    256
#define HDIM    256
#define VDIM    42
#define TSTEPS  128

// ---------------------------------------------------------------------------
// Static device scratch
// ---------------------------------------------------------------------------
__device__ float g_act0[(size_t)BATCH * 2048];
__device__ float g_act1[(size_t)BATCH * 1024];
__device__ float g_giA [(size_t)BATCH * 1536];                    // (gi0 | gh1)
__device__ float g_gh0 [(size_t)BATCH * 768];
__device__ float g_gi1 [(size_t)BATCH * 768];
__device__ float g_h0  [(size_t)BATCH * HDIM];
__device__ float g_hist[(size_t)(TSTEPS + 1) * BATCH * HDIM];     // slot s = h1_{s-1}
__device__ float g_wcat[1536 * HDIM];                             // [wih0 ; whh1]
__device__ float g_bcat[1536];

// ---------------------------------------------------------------------------
// Helpers
// ---------------------------------------------------------------------------
__device__ __forceinline__ uint32_t smem_u32(const void* p) {
    return (uint32_t)__cvta_generic_to_shared(p);
}
__device__ __forceinline__ void cp_async16(uint32_t dst, const void* src, int bytes) {
    asm volatile("cp.async.cg.shared.global [%0], [%1], 16, %2;\n"
                 :: "r"(dst), "l"(src), "r"(bytes));
}
__device__ __forceinline__ uint32_t f2tf32(float x) {
    uint32_t r;
    asm("cvt.rna.tf32.f32 %0, %1;" : "=r"(r) : "f"(x));
    return r;
}
__device__ __forceinline__ void mma_tf32(float c[4], const uint32_t a[4], const uint32_t b[2]) {
    asm volatile("mma.sync.aligned.m16n8k8.row.col.f32.tf32.tf32.f32 "
                 "{%0,%1,%2,%3}, {%4,%5,%6,%7}, {%8,%9}, {%0,%1,%2,%3};"
                 : "+f"(c[0]), "+f"(c[1]), "+f"(c[2]), "+f"(c[3])
                 : "r"(a[0]), "r"(a[1]), "r"(a[2]), "r"(a[3]),
                   "r"(b[0]), "r"(b[1]));
}

// ---------------------------------------------------------------------------
// TF32 tensor-core GEMM:  C[M,N] = A[M,K] @ W[N,K]^T + bias[N] (+ReLU)
// CTA tile 128x128, warp tile 64x32, BK=32, 2-stage cp.async pipeline.
// M, N must be multiples of 128 (true for all call sites); K % 4 == 0.
// SMEM pitch 36 words -> conflict-free 32-bit fragment loads.
// ---------------------------------------------------------------------------
#define GPITCH 36
#define GSTAGE (128 * GPITCH)                 // floats per tile per stage
#define GSMEM_BYTES (4 * GSTAGE * 4 * 2 / 2)  // 2 tiles * 2 stages * 128*36*4 = 73728

template<bool RELU>
__global__ void __launch_bounds__(256, 2)
gemm_tf32(const float* __restrict__ A, int lda,
          const float* __restrict__ W,              // N x K row-major
          const float* __restrict__ bias,
          float* __restrict__ C, int ldc,
          int K)
{
    extern __shared__ float sm[];
    float* As = sm;                 // [2][128][GPITCH]
    float* Ws = sm + 2 * GSTAGE;    // [2][128][GPITCH]

    const int tid  = threadIdx.x;
    const int bm   = blockIdx.y * 128;
    const int bn   = blockIdx.x * 128;
    const int w    = tid >> 5;
    const int lane = tid & 31;
    const int wm   = (w & 1) * 64;      // 2 warps in M
    const int wn   = (w >> 1) * 32;     // 4 warps in N
    const int g    = lane >> 2;         // group 0..7
    const int tg   = lane & 3;          // thread-in-group 0..3

    float acc[4][4][4];
    #pragma unroll
    for (int i = 0; i < 4; i++)
        #pragma unroll
        for (int j = 0; j < 4; j++)
            #pragma unroll
            for (int q = 0; q < 4; q++) acc[i][j][q] = 0.f;

    const int KT = (K + 31) / 32;

    // per-thread load slots: 4 chunks of A, 4 of W per stage (16B each)
    const int lrow = tid >> 3;          // 0..31 (row mod 32 group base)
    const int lcc  = (tid & 7) * 4;     // k-word offset within BK (0,4,...,28)

    auto issue = [&](int kt, int st) {
        const int k = kt * 32 + lcc;
        const int bytes = (k < K) ? 16 : 0;
        const int koff  = (k < K) ? k : 0;
        float* as = As + st * GSTAGE;
        float* ws = Ws + st * GSTAGE;
        #pragma unroll
        for (int i = 0; i < 4; i++) {
            const int r = lrow + i * 32;
            cp_async16(smem_u32(as + r * GPITCH + lcc),
                       A + (size_t)(bm + r) * lda + koff, bytes);
            cp_async16(smem_u32(ws + r * GPITCH + lcc),
                       W + (size_t)(bn + r) * K + koff, bytes);
        }
        asm volatile("cp.async.commit_group;\n");
    };

    issue(0, 0);

    for (int kt = 0; kt < KT; kt++) {
        if (kt + 1 < KT) issue(kt + 1, (kt + 1) & 1);
        else             asm volatile("cp.async.commit_group;\n");
        asm volatile("cp.async.wait_group 1;\n");
        __syncthreads();

        const float* as = As + (kt & 1) * GSTAGE + wm * GPITCH;
        const float* ws = Ws + (kt & 1) * GSTAGE + wn * GPITCH;

        #pragma unroll
        for (int kk = 0; kk < 4; kk++) {
            const int kb = kk * 8;
            uint32_t af[4][4], bf[4][2];
            #pragma unroll
            for (int i = 0; i < 4; i++) {
                const float* b0 = as + (i * 16) * GPITCH + kb;
                af[i][0] = f2tf32(b0[(g    ) * GPITCH + tg    ]);
                af[i][1] = f2tf32(b0[(g + 8) * GPITCH + tg    ]);
                af[i][2] = f2tf32(b0[(g    ) * GPITCH + tg + 4]);
                af[i][3] = f2tf32(b0[(g + 8) * GPITCH + tg + 4]);
            }
            #pragma unroll
            for (int j = 0; j < 4; j++) {
                const float* b0 = ws + (j * 8) * GPITCH + kb;
                bf[j][0] = f2tf32(b0[g * GPITCH + tg    ]);
                bf[j][1] = f2tf32(b0[g * GPITCH + tg + 4]);
            }
            #pragma unroll
            for (int i = 0; i < 4; i++)
                #pragma unroll
                for (int j = 0; j < 4; j++)
                    mma_tf32(acc[i][j], af[i], bf[j]);
        }
        __syncthreads();
    }

    // epilogue: bias (+ReLU), STG.64
    float bx[4], by[4];
    #pragma unroll
    for (int j = 0; j < 4; j++) {
        const int n = bn + wn + j * 8 + 2 * tg;
        bx[j] = bias[n];
        by[j] = bias[n + 1];
    }
    #pragma unroll
    for (int i = 0; i < 4; i++) {
        const int r0 = bm + wm + i * 16 + g;
        #pragma unroll
        for (int j = 0; j < 4; j++) {
            const int n = bn + wn + j * 8 + 2 * tg;
            float2 v0, v1;
            v0.x = acc[i][j][0] + bx[j]; v0.y = acc[i][j][1] + by[j];
            v1.x = acc[i][j][2] + bx[j]; v1.y = acc[i][j][3] + by[j];
            if (RELU) {
                v0.x = fmaxf(v0.x, 0.f); v0.y = fmaxf(v0.y, 0.f);
                v1.x = fmaxf(v1.x, 0.f); v1.y = fmaxf(v1.y, 0.f);
            }
            *(float2*)&C[(size_t)r0       * ldc + n] = v0;
            *(float2*)&C[(size_t)(r0 + 8) * ldc + n] = v1;
        }
    }
}

// ---------------------------------------------------------------------------
// GRU gate elementwise
// ---------------------------------------------------------------------------
__device__ __forceinline__ float sigmoidf_(float x) { return 1.f / (1.f + expf(-x)); }

__global__ void gru_gates_kernel(const float* __restrict__ gi, int ldi,
                                 const float* __restrict__ gh, int ldh,
                                 const float* __restrict__ hprev,
                                 float* __restrict__ hnew)
{
    const int idx = blockIdx.x * blockDim.x + threadIdx.x;
    if (idx >= BATCH * HDIM) return;
    const int b = idx / HDIM;
    const int i = idx % HDIM;
    const float* gir = gi + (size_t)b * ldi;
    const float* ghr = gh + (size_t)b * ldh;
    const float r = sigmoidf_(gir[i]           + ghr[i]);
    const float z = sigmoidf_(gir[HDIM + i]    + ghr[HDIM + i]);
    const float n = tanhf   (gir[2 * HDIM + i] + r * ghr[2 * HDIM + i]);
    hnew[idx] = (1.f - z) * n + z * hprev[idx];
}

// ---------------------------------------------------------------------------
// Prep / init kernels
// ---------------------------------------------------------------------------
__global__ void prep_wcat_kernel(const float* __restrict__ wih0,
                                 const float* __restrict__ whh1,
                                 const float* __restrict__ bih0,
                                 const float* __restrict__ bhh1)
{
    const int idx = blockIdx.x * blockDim.x + threadIdx.x;
    const int half = 768 * HDIM;
    if (idx < half)          g_wcat[idx] = wih0[idx];
    else if (idx < 2 * half) g_wcat[idx] = whh1[idx - half];
    if (idx < 768)           g_bcat[idx] = bih0[idx];
    else if (idx < 1536)     g_bcat[idx] = bhh1[idx - 768];
}

__global__ void zero_kernel(float* __restrict__ p, int n)
{
    const int idx = blockIdx.x * blockDim.x + threadIdx.x;
    if (idx < n) p[idx] = 0.f;
}

// ---------------------------------------------------------------------------
// Fused FC + ReLU + softmax (V=42), one warp per (b, t)
// ---------------------------------------------------------------------------
__global__ void __launch_bounds__(256)
fc_softmax_kernel(const float* __restrict__ hist,
                  const float* __restrict__ wfc,
                  const float* __restrict__ bfc,
                  float* __restrict__ out)
{
    const int gwarp = (blockIdx.x * blockDim.x + threadIdx.x) >> 5;
    const int lane  = threadIdx.x & 31;
    const int wl    = threadIdx.x >> 5;
    if (gwarp >= BATCH * TSTEPS) return;
    const int b = gwarp / TSTEPS;
    const int t = gwarp % TSTEPS;

    __shared__ float hs[8][HDIM];
    const float* h = hist + ((size_t)(t + 1) * BATCH + b) * HDIM;
    #pragma unroll
    for (int k = 0; k < HDIM / 32; k++) hs[wl][lane + k * 32] = h[lane + k * 32];
    __syncwarp();

    const float* hrow = hs[wl];
    const bool has2 = (lane < VDIM - 32);

    float v0 = bfc[lane];
    {
        const float4* w4 = (const float4*)&wfc[(size_t)lane * HDIM];
        float a = 0.f;
        #pragma unroll 8
        for (int k = 0; k < HDIM / 4; k++) {
            const float4 wv = w4[k];
            const float4 hv = *(const float4*)&hrow[k * 4];
            a += wv.x * hv.x + wv.y * hv.y + wv.z * hv.z + wv.w * hv.w;
        }
        v0 += a;
    }
    float v1 = -1e30f;
    if (has2) {
        v1 = bfc[lane + 32];
        const float4* w4 = (const float4*)&wfc[(size_t)(lane + 32) * HDIM];
        float a = 0.f;
        #pragma unroll 8
        for (int k = 0; k < HDIM / 4; k++) {
            const float4 wv = w4[k];
            const float4 hv = *(const float4*)&hrow[k * 4];
            a += wv.x * hv.x + wv.y * hv.y + wv.z * hv.z + wv.w * hv.w;
        }
        v1 += a;
    }

    v0 = fmaxf(v0, 0.f);
    const float lv1 = has2 ? fmaxf(v1, 0.f) : -1e30f;

    float m = fmaxf(v0, lv1);
    #pragma unroll
    for (int off = 16; off; off >>= 1) m = fmaxf(m, __shfl_xor_sync(0xffffffffu, m, off));

    const float e0 = expf(v0 - m);
    const float e1 = has2 ? expf(lv1 - m) : 0.f;
    float s = e0 + e1;
    #pragma unroll
    for (int off = 16; off; off >>= 1) s += __shfl_xor_sync(0xffffffffu, s, off);

    const float inv = 1.f / s;
    float* o = out + (size_t)gwarp * VDIM;
    o[lane] = e0 * inv;
    if (has2) o[lane + 32] = e1 * inv;
}

// ---------------------------------------------------------------------------
// Launch
// ---------------------------------------------------------------------------
extern "C" void kernel_launch(void* const* d_in, const int* in_sizes, int n_in,
                              void* d_out, int out_size)
{
    const float* x    = (const float*)d_in[0];
    const float* w1   = (const float*)d_in[1];
    const float* b1   = (const float*)d_in[2];
    const float* w2   = (const float*)d_in[3];
    const float* b2   = (const float*)d_in[4];
    const float* w3   = (const float*)d_in[5];
    const float* b3   = (const float*)d_in[6];
    const float* w4   = (const float*)d_in[7];
    const float* b4   = (const float*)d_in[8];
    const float* wih0 = (const float*)d_in[9];
    const float* whh0 = (const float*)d_in[10];
    const float* bih0 = (const float*)d_in[11];
    const float* bhh0 = (const float*)d_in[12];
    const float* wih1 = (const float*)d_in[13];
    const float* whh1 = (const float*)d_in[14];
    const float* bih1 = (const float*)d_in[15];
    const float* bhh1 = (const float*)d_in[16];
    const float* wfc  = (const float*)d_in[17];
    const float* bfc  = (const float*)d_in[18];
    float* out = (float*)d_out;

    float *act0, *act1, *giA, *gh0, *gi1, *h0, *hist, *wcat, *bcat;
    cudaGetSymbolAddress((void**)&act0, g_act0);
    cudaGetSymbolAddress((void**)&act1, g_act1);
    cudaGetSymbolAddress((void**)&giA,  g_giA);
    cudaGetSymbolAddress((void**)&gh0,  g_gh0);
    cudaGetSymbolAddress((void**)&gi1,  g_gi1);
    cudaGetSymbolAddress((void**)&h0,   g_h0);
    cudaGetSymbolAddress((void**)&hist, g_hist);
    cudaGetSymbolAddress((void**)&wcat, g_wcat);
    cudaGetSymbolAddress((void**)&bcat, g_bcat);

    static bool attr_set = false;
    if (!attr_set) {
        cudaFuncSetAttribute(gemm_tf32<true>,
            cudaFuncAttributeMaxDynamicSharedMemorySize, GSMEM_BYTES);
        cudaFuncSetAttribute(gemm_tf32<false>,
            cudaFuncAttributeMaxDynamicSharedMemorySize, GSMEM_BYTES);
        attr_set = true;
    }

    const int BH = BATCH * HDIM;

    zero_kernel<<<(BH + 255) / 256, 256>>>(h0, BH);
    zero_kernel<<<(BH + 255) / 256, 256>>>(hist, BH);
    prep_wcat_kernel<<<(1536 * HDIM + 255) / 256, 256>>>(wih0, whh1, bih0, bhh1);

    // ---- encoder MLP ----
    gemm_tf32<true><<<dim3(2048 / 128, BATCH / 128), 256, GSMEM_BYTES>>>(x,    FPDIM, w1, b1, act0, 2048, FPDIM);
    gemm_tf32<true><<<dim3(1024 / 128, BATCH / 128), 256, GSMEM_BYTES>>>(act0, 2048,  w2, b2, act1, 1024, 2048);
    gemm_tf32<true><<<dim3(512  / 128, BATCH / 128), 256, GSMEM_BYTES>>>(act1, 1024,  w3, b3, act0, 512,  1024);
    gemm_tf32<true><<<dim3(256  / 128, BATCH / 128), 256, GSMEM_BYTES>>>(act0, 512,   w4, b4, act1, 256,  512);
    const float* e = act1;   // (B, E)

    // ---- GRU over T steps ----
    const dim3 g768 (768  / 128, BATCH / 128);
    const dim3 g1536(1536 / 128, BATCH / 128);
    const int gatesBlocks = (BH + 255) / 256;

    for (int t = 0; t < TSTEPS; t++) {
        const float* h1prev = hist + (size_t)t * BH;
        float*       h1new  = hist + (size_t)(t + 1) * BH;

        if (t == 0) {
            gemm_tf32<false><<<g768, 256, GSMEM_BYTES>>>(e,      EDIM, wih0, bih0, giA,       1536, EDIM);
            gemm_tf32<false><<<g768, 256, GSMEM_BYTES>>>(h1prev, HDIM, whh1, bhh1, giA + 768, 1536, HDIM);
        } else {
            gemm_tf32<false><<<g1536, 256, GSMEM_BYTES>>>(h1prev, HDIM, wcat, bcat, giA, 1536, HDIM);
        }
        gemm_tf32<false><<<g768, 256, GSMEM_BYTES>>>(h0, HDIM, whh0, bhh0, gh0, 768, HDIM);
        gru_gates_kernel<<<gatesBlocks, 256>>>(giA, 1536, gh0, 768, h0, h0);
        gemm_tf32<false><<<g768, 256, GSMEM_BYTES>>>(h0, HDIM, wih1, bih1, gi1, 768, HDIM);
        gru_gates_kernel<<<gatesBlocks, 256>>>(gi1, 768, giA + 768, 1536, h1prev, h1new);
    }

    // ---- fused FC + ReLU + softmax ----
    const long long totalWarps = (long long)BATCH * TSTEPS;
    const int fcBlocks = (int)((totalWarps * 32 + 255) / 256);
    fc_softmax_kernel<<<fcBlocks, 256>>>(hist, wfc, bfc, out);
}

// round 4
// speedup vs baseline: 2.6057x; 1.1946x over previous
#include <cuda_runtime.h>
#include <math.h>
#include <stdint.h>

#define BATCH   8192
#define FPDIM   4860
#define EDIM    256
#define HDIM    256
#define VDIM    42
#define TSTEPS  128

// ---------------------------------------------------------------------------
// Static device scratch
// ---------------------------------------------------------------------------
__device__ float g_act0[(size_t)BATCH * 2048];
__device__ float g_act1[(size_t)BATCH * 1024];
__device__ float g_giA [(size_t)BATCH * 1536];                 // (gi0 | gh1)
__device__ float g_gh0 [(size_t)BATCH * 768];
__device__ float g_gi1 [(size_t)BATCH * 768];
__device__ float g_h0  [(size_t)BATCH * HDIM];
__device__ float g_hist[(size_t)(TSTEPS + 1) * BATCH * HDIM];  // slot s = h1_{s-1}, K-permuted tf32-rounded

// pre-rounded, K-permuted weights
__device__ float g_w1r  [(size_t)2048 * 4864];
__device__ float g_w2r  [(size_t)1024 * 2048];
__device__ float g_w3r  [(size_t)512 * 1024];
__device__ float g_w4r  [(size_t)256 * 512];
__device__ float g_wcat [(size_t)1536 * 256];                  // [wih0 ; whh1]
__device__ float g_whh0r[(size_t)768 * 256];
__device__ float g_wih1r[(size_t)768 * 256];
__device__ float g_wfcp [(size_t)VDIM * 256];                  // permuted, NOT rounded
__device__ float g_bcat [1536];

// ---------------------------------------------------------------------------
// helpers
// ---------------------------------------------------------------------------
__device__ __forceinline__ uint32_t smem_u32(const void* p) {
    return (uint32_t)__cvta_generic_to_shared(p);
}
__device__ __forceinline__ void cp_async16(uint32_t dst, const void* src, int bytes) {
    asm volatile("cp.async.cg.shared.global [%0], [%1], 16, %2;\n"
                 :: "r"(dst), "l"(src), "r"(bytes));
}
#define CP_COMMIT()  asm volatile("cp.async.commit_group;\n")
#define CP_WAIT1()   asm volatile("cp.async.wait_group 1;\n")

__device__ __forceinline__ uint32_t f2tf32(float x) {
    uint32_t r;
    asm("cvt.rna.tf32.f32 %0, %1;" : "=r"(r) : "f"(x));
    return r;
}
__device__ __forceinline__ float rnd_tf32(float x) {
    return __uint_as_float(f2tf32(x));
}
__device__ __forceinline__ void mma_tf32(float c[4], const uint32_t a[4], const uint32_t b[2]) {
    asm volatile("mma.sync.aligned.m16n8k8.row.col.f32.tf32.tf32.f32 "
                 "{%0,%1,%2,%3}, {%4,%5,%6,%7}, {%8,%9}, {%0,%1,%2,%3};"
                 : "+f"(c[0]), "+f"(c[1]), "+f"(c[2]), "+f"(c[3])
                 : "r"(a[0]), "r"(a[1]), "r"(a[2]), "r"(a[3]),
                   "r"(b[0]), "r"(b[1]));
}

// ---------------------------------------------------------------------------
// TF32 tensor GEMM:  C[M,N] = A[M,K] @ W[N,K]^T + bias[N]
// CTA 128x128, warp 64x32, BK=32, 2-stage cp.async.
// W pre-rounded + K-permuted (pairs [k,k+4] adjacent). A likewise unless CVTA.
// Supports 2 fused problems split along grid.x.
// ---------------------------------------------------------------------------
#define GP     40                         // smem pitch (words)
#define GT     (128 * GP)                 // words per tile per stage
#define GSMEM_BYTES (4 * GT * 4)          // 2 tiles * 2 stages * 4B = 81920

struct GemmP { const float* A; const float* W; const float* bias; float* C; int ldc; };

template<bool RELU, bool ROUND, bool CVTA>
__global__ void __launch_bounds__(256, 2)
gemm_tc(GemmP p0, GemmP p1, int split, int lda, int K, int KB)
{
    extern __shared__ float sm[];   // [A s0][A s1][W s0][W s1]

    const int tid  = threadIdx.x;
    int bxx = blockIdx.x;
    GemmP P = p0;
    if (bxx >= split) { P = p1; bxx -= split; }
    const int bm = blockIdx.y * 128;
    const int bn = bxx * 128;

    const int w    = tid >> 5;
    const int lane = tid & 31;
    const int wm   = (w & 1) * 64;
    const int wn   = (w >> 1) * 32;
    const int g    = lane >> 2;
    const int tg   = lane & 3;

    float acc[4][4][4];
    #pragma unroll
    for (int i = 0; i < 4; i++)
        #pragma unroll
        for (int j = 0; j < 4; j++)
            #pragma unroll
            for (int q = 0; q < 4; q++) acc[i][j][q] = 0.f;

    const int KT   = (K + 31) / 32;
    const int lrow = tid >> 3;           // 0..31
    const int lcw  = (tid & 7) * 4;      // word offset in BK

    const float* A = P.A;
    const float* W = P.W;

    auto issue = [&](int kt, int st) {
        const int k = kt * 32 + lcw;
        float* as = sm + st * GT;
        float* ws = sm + (2 + st) * GT;
        const int abytes = (k < K)  ? 16 : 0;
        const int ak     = (k < K)  ? k  : 0;
        const int wbytes = (k < KB) ? 16 : 0;
        const int wk     = (k < KB) ? k  : 0;
        #pragma unroll
        for (int i = 0; i < 4; i++) {
            const int r = lrow + i * 32;
            cp_async16(smem_u32(as + r * GP + lcw), A + (size_t)(bm + r) * lda + ak, abytes);
            cp_async16(smem_u32(ws + r * GP + lcw), W + (size_t)(bn + r) * KB  + wk, wbytes);
        }
        CP_COMMIT();
    };

    issue(0, 0);

    for (int kt = 0; kt < KT; kt++) {
        if (kt + 1 < KT) issue(kt + 1, (kt + 1) & 1);
        else             CP_COMMIT();
        CP_WAIT1();
        __syncthreads();

        const float* as = sm + (kt & 1) * GT + wm * GP;
        const float* ws = sm + (2 + (kt & 1)) * GT + wn * GP;

        #pragma unroll
        for (int kk = 0; kk < 4; kk++) {
            const int kb = kk * 8;
            uint32_t af[4][4], bf[4][2];
            if (CVTA) {
                #pragma unroll
                for (int i = 0; i < 4; i++) {
                    const float* b0 = as + (i * 16) * GP + kb;
                    af[i][0] = f2tf32(b0[(g    ) * GP + tg    ]);
                    af[i][1] = f2tf32(b0[(g + 8) * GP + tg    ]);
                    af[i][2] = f2tf32(b0[(g    ) * GP + tg + 4]);
                    af[i][3] = f2tf32(b0[(g + 8) * GP + tg + 4]);
                }
            } else {
                #pragma unroll
                for (int i = 0; i < 4; i++) {
                    const uint2 v0 = *(const uint2*)(as + (i * 16 + g    ) * GP + kb + 2 * tg);
                    const uint2 v1 = *(const uint2*)(as + (i * 16 + g + 8) * GP + kb + 2 * tg);
                    af[i][0] = v0.x; af[i][2] = v0.y;
                    af[i][1] = v1.x; af[i][3] = v1.y;
                }
            }
            #pragma unroll
            for (int j = 0; j < 4; j++) {
                const uint2 vb = *(const uint2*)(ws + (j * 8 + g) * GP + kb + 2 * tg);
                bf[j][0] = vb.x; bf[j][1] = vb.y;
            }
            #pragma unroll
            for (int i = 0; i < 4; i++)
                #pragma unroll
                for (int j = 0; j < 4; j++)
                    mma_tf32(acc[i][j], af[i], bf[j]);
        }
        __syncthreads();
    }

    const float* bias = P.bias;
    float* C = P.C;
    const int ldc = P.ldc;

    if (!ROUND) {
        // natural layout STG.64 (GRU gate pre-activations)
        float bx[4], by[4];
        #pragma unroll
        for (int j = 0; j < 4; j++) {
            const int n = bn + wn + j * 8 + 2 * tg;
            bx[j] = bias[n]; by[j] = bias[n + 1];
        }
        #pragma unroll
        for (int i = 0; i < 4; i++) {
            const int r0 = bm + wm + i * 16 + g;
            #pragma unroll
            for (int j = 0; j < 4; j++) {
                const int n = bn + wn + j * 8 + 2 * tg;
                float2 v0, v1;
                v0.x = acc[i][j][0] + bx[j]; v0.y = acc[i][j][1] + by[j];
                v1.x = acc[i][j][2] + bx[j]; v1.y = acc[i][j][3] + by[j];
                if (RELU) {
                    v0.x = fmaxf(v0.x, 0.f); v0.y = fmaxf(v0.y, 0.f);
                    v1.x = fmaxf(v1.x, 0.f); v1.y = fmaxf(v1.y, 0.f);
                }
                *(float2*)&C[(size_t)r0       * ldc + n] = v0;
                *(float2*)&C[(size_t)(r0 + 8) * ldc + n] = v1;
            }
        }
    } else {
        // tf32-rounded + K-permuted store (feeds another GEMM as A)
        const int p0 = (tg < 2) ? 4 * tg : 4 * tg - 7;   // perm of col 2tg
        const int p1 = p0 + 2;                           // perm of col 2tg+1
        #pragma unroll
        for (int i = 0; i < 4; i++) {
            const int r0 = bm + wm + i * 16 + g;
            #pragma unroll
            for (int j = 0; j < 4; j++) {
                const int nb = bn + wn + j * 8;
                float u0 = acc[i][j][0] + bias[nb + 2 * tg];
                float u1 = acc[i][j][1] + bias[nb + 2 * tg + 1];
                float u2 = acc[i][j][2] + bias[nb + 2 * tg];
                float u3 = acc[i][j][3] + bias[nb + 2 * tg + 1];
                if (RELU) {
                    u0 = fmaxf(u0, 0.f); u1 = fmaxf(u1, 0.f);
                    u2 = fmaxf(u2, 0.f); u3 = fmaxf(u3, 0.f);
                }
                C[(size_t)r0       * ldc + nb + p0] = rnd_tf32(u0);
                C[(size_t)r0       * ldc + nb + p1] = rnd_tf32(u1);
                C[(size_t)(r0 + 8) * ldc + nb + p0] = rnd_tf32(u2);
                C[(size_t)(r0 + 8) * ldc + nb + p1] = rnd_tf32(u3);
            }
        }
    }
}

// ---------------------------------------------------------------------------
// GRU gates: 8 logical elements (one k-group) per thread.
// gi/gh natural layout; hprev/hnew K-permuted tf32-rounded.
// ---------------------------------------------------------------------------
__device__ __forceinline__ float sig_(float x)  { return 1.f / (1.f + __expf(-x)); }
__device__ __forceinline__ float tanh_(float x) { float e = __expf(2.f * x); return 1.f - 2.f / (e + 1.f); }

__global__ void gru_gates(const float* __restrict__ gi, int ldi,
                          const float* __restrict__ gh, int ldh,
                          const float* __restrict__ hprev,
                          float* __restrict__ hnew)
{
    const int idx = blockIdx.x * blockDim.x + threadIdx.x;
    if (idx >= BATCH * HDIM / 8) return;
    const int b = idx >> 5;
    const int q = (idx & 31) * 8;

    const float* gib = gi + (size_t)b * ldi + q;
    const float* ghb = gh + (size_t)b * ldh + q;

    float ir[8], iz[8], in_[8], hr[8], hz[8], hn[8];
    *(float4*)&ir[0]  = *(const float4*)(gib);
    *(float4*)&ir[4]  = *(const float4*)(gib + 4);
    *(float4*)&iz[0]  = *(const float4*)(gib + 256);
    *(float4*)&iz[4]  = *(const float4*)(gib + 260);
    *(float4*)&in_[0] = *(const float4*)(gib + 512);
    *(float4*)&in_[4] = *(const float4*)(gib + 516);
    *(float4*)&hr[0]  = *(const float4*)(ghb);
    *(float4*)&hr[4]  = *(const float4*)(ghb + 4);
    *(float4*)&hz[0]  = *(const float4*)(ghb + 256);
    *(float4*)&hz[4]  = *(const float4*)(ghb + 260);
    *(float4*)&hn[0]  = *(const float4*)(ghb + 512);
    *(float4*)&hn[4]  = *(const float4*)(ghb + 516);

    const float* hp = hprev + (size_t)b * HDIM + q;
    const float4 h0v = *(const float4*)hp;        // logical {0,4,1,5}
    const float4 h1v = *(const float4*)(hp + 4);  // logical {2,6,3,7}
    float hpl[8];
    hpl[0] = h0v.x; hpl[4] = h0v.y; hpl[1] = h0v.z; hpl[5] = h0v.w;
    hpl[2] = h1v.x; hpl[6] = h1v.y; hpl[3] = h1v.z; hpl[7] = h1v.w;

    float h[8];
    #pragma unroll
    for (int k = 0; k < 8; k++) {
        const float r = sig_(ir[k] + hr[k]);
        const float z = sig_(iz[k] + hz[k]);
        const float n = tanh_(in_[k] + r * hn[k]);
        h[k] = (1.f - z) * n + z * hpl[k];
    }

    float4 o0, o1;
    o0.x = rnd_tf32(h[0]); o0.y = rnd_tf32(h[4]); o0.z = rnd_tf32(h[1]); o0.w = rnd_tf32(h[5]);
    o1.x = rnd_tf32(h[2]); o1.y = rnd_tf32(h[6]); o1.z = rnd_tf32(h[3]); o1.w = rnd_tf32(h[7]);
    float* hv = hnew + (size_t)b * HDIM + q;
    *(float4*)hv       = o0;
    *(float4*)(hv + 4) = o1;
}

// ---------------------------------------------------------------------------
// setup: K-permute (+ optional tf32 round) a weight matrix, zero-pad K->Kpad
// ---------------------------------------------------------------------------
__global__ void perm_w(const float* __restrict__ src, float* __restrict__ dst,
                       int N, int K, int Kpad, int do_round)
{
    const int idx = blockIdx.x * blockDim.x + threadIdx.x;
    if (idx >= N * Kpad) return;
    const int row = idx / Kpad;
    const int p   = idx % Kpad;
    const int grp = p >> 3, wi = p & 7;
    const int k   = (grp << 3) + ((wi & 1) ? (wi >> 1) + 4 : (wi >> 1));
    float v = (k < K) ? src[(size_t)row * K + k] : 0.f;
    dst[idx] = do_round ? rnd_tf32(v) : v;
}

__global__ void prep_bcat(const float* __restrict__ bih0, const float* __restrict__ bhh1)
{
    const int idx = blockIdx.x * blockDim.x + threadIdx.x;
    if (idx < 768)            g_bcat[idx] = bih0[idx];
    else if (idx < 1536)      g_bcat[idx] = bhh1[idx - 768];
}

__global__ void zero_kernel(float* __restrict__ p, int n)
{
    const int idx = blockIdx.x * blockDim.x + threadIdx.x;
    if (idx < n) p[idx] = 0.f;
}

// ---------------------------------------------------------------------------
// Fused FC + ReLU + softmax (V=42), one warp per (b, t).
// hist and wfcp are identically K-permuted -> dot product invariant.
// ---------------------------------------------------------------------------
__global__ void __launch_bounds__(256)
fc_softmax_kernel(const float* __restrict__ hist,
                  const float* __restrict__ wfc,
                  const float* __restrict__ bfc,
                  float* __restrict__ out)
{
    const int gwarp = (blockIdx.x * blockDim.x + threadIdx.x) >> 5;
    const int lane  = threadIdx.x & 31;
    const int wl    = threadIdx.x >> 5;
    if (gwarp >= BATCH * TSTEPS) return;
    const int b = gwarp / TSTEPS;
    const int t = gwarp % TSTEPS;

    __shared__ float hs[8][HDIM];
    const float* h = hist + ((size_t)(t + 1) * BATCH + b) * HDIM;
    #pragma unroll
    for (int k = 0; k < HDIM / 32; k++) hs[wl][lane + k * 32] = h[lane + k * 32];
    __syncwarp();

    const float* hrow = hs[wl];
    const bool has2 = (lane < VDIM - 32);

    float v0 = bfc[lane];
    {
        const float4* w4 = (const float4*)&wfc[(size_t)lane * HDIM];
        float a = 0.f;
        #pragma unroll 8
        for (int k = 0; k < HDIM / 4; k++) {
            const float4 wv = w4[k];
            const float4 hv = *(const float4*)&hrow[k * 4];
            a += wv.x * hv.x + wv.y * hv.y + wv.z * hv.z + wv.w * hv.w;
        }
        v0 += a;
    }
    float v1 = -1e30f;
    if (has2) {
        v1 = bfc[lane + 32];
        const float4* w4 = (const float4*)&wfc[(size_t)(lane + 32) * HDIM];
        float a = 0.f;
        #pragma unroll 8
        for (int k = 0; k < HDIM / 4; k++) {
            const float4 wv = w4[k];
            const float4 hv = *(const float4*)&hrow[k * 4];
            a += wv.x * hv.x + wv.y * hv.y + wv.z * hv.z + wv.w * hv.w;
        }
        v1 += a;
    }

    v0 = fmaxf(v0, 0.f);
    const float lv1 = has2 ? fmaxf(v1, 0.f) : -1e30f;

    float m = fmaxf(v0, lv1);
    #pragma unroll
    for (int off = 16; off; off >>= 1) m = fmaxf(m, __shfl_xor_sync(0xffffffffu, m, off));

    const float e0 = expf(v0 - m);
    const float e1 = has2 ? expf(lv1 - m) : 0.f;
    float s = e0 + e1;
    #pragma unroll
    for (int off = 16; off; off >>= 1) s += __shfl_xor_sync(0xffffffffu, s, off);

    const float inv = 1.f / s;
    float* o = out + (size_t)gwarp * VDIM;
    o[lane] = e0 * inv;
    if (has2) o[lane + 32] = e1 * inv;
}

// ---------------------------------------------------------------------------
// Launch
// ---------------------------------------------------------------------------
extern "C" void kernel_launch(void* const* d_in, const int* in_sizes, int n_in,
                              void* d_out, int out_size)
{
    const float* x    = (const float*)d_in[0];
    const float* w1   = (const float*)d_in[1];
    const float* b1   = (const float*)d_in[2];
    const float* w2   = (const float*)d_in[3];
    const float* b2   = (const float*)d_in[4];
    const float* w3   = (const float*)d_in[5];
    const float* b3   = (const float*)d_in[6];
    const float* w4   = (const float*)d_in[7];
    const float* b4   = (const float*)d_in[8];
    const float* wih0 = (const float*)d_in[9];
    const float* whh0 = (const float*)d_in[10];
    const float* bih0 = (const float*)d_in[11];
    const float* bhh0 = (const float*)d_in[12];
    const float* wih1 = (const float*)d_in[13];
    const float* whh1 = (const float*)d_in[14];
    const float* bih1 = (const float*)d_in[15];
    const float* bhh1 = (const float*)d_in[16];
    const float* wfc  = (const float*)d_in[17];
    const float* bfc  = (const float*)d_in[18];
    float* out = (float*)d_out;

    float *act0, *act1, *giA, *gh0, *gi1, *h0, *hist;
    float *w1r, *w2r, *w3r, *w4r, *wcat, *whh0r, *wih1r, *wfcp, *bcat;
    cudaGetSymbolAddress((void**)&act0,  g_act0);
    cudaGetSymbolAddress((void**)&act1,  g_act1);
    cudaGetSymbolAddress((void**)&giA,   g_giA);
    cudaGetSymbolAddress((void**)&gh0,   g_gh0);
    cudaGetSymbolAddress((void**)&gi1,   g_gi1);
    cudaGetSymbolAddress((void**)&h0,    g_h0);
    cudaGetSymbolAddress((void**)&hist,  g_hist);
    cudaGetSymbolAddress((void**)&w1r,   g_w1r);
    cudaGetSymbolAddress((void**)&w2r,   g_w2r);
    cudaGetSymbolAddress((void**)&w3r,   g_w3r);
    cudaGetSymbolAddress((void**)&w4r,   g_w4r);
    cudaGetSymbolAddress((void**)&wcat,  g_wcat);
    cudaGetSymbolAddress((void**)&whh0r, g_whh0r);
    cudaGetSymbolAddress((void**)&wih1r, g_wih1r);
    cudaGetSymbolAddress((void**)&wfcp,  g_wfcp);
    cudaGetSymbolAddress((void**)&bcat,  g_bcat);

    static bool attr_set = false;
    if (!attr_set) {
        cudaFuncSetAttribute(gemm_tc<true,  true,  true >, cudaFuncAttributeMaxDynamicSharedMemorySize, GSMEM_BYTES);
        cudaFuncSetAttribute(gemm_tc<true,  true,  false>, cudaFuncAttributeMaxDynamicSharedMemorySize, GSMEM_BYTES);
        cudaFuncSetAttribute(gemm_tc<false, false, false>, cudaFuncAttributeMaxDynamicSharedMemorySize, GSMEM_BYTES);
        attr_set = true;
    }

    const int BH = BATCH * HDIM;

    // ---- one-time prep (replayed; deterministic) ----
    #define PERM(src, dst, N, K, Kp, rnd) \
        perm_w<<<((N) * (Kp) + 255) / 256, 256>>>(src, dst, N, K, Kp, rnd)
    PERM(w1,   w1r,          2048, 4860, 4864, 1);
    PERM(w2,   w2r,          1024, 2048, 2048, 1);
    PERM(w3,   w3r,           512, 1024, 1024, 1);
    PERM(w4,   w4r,           256,  512,  512, 1);
    PERM(wih0, wcat,          768,  256,  256, 1);
    PERM(whh1, wcat + 768*256,768,  256,  256, 1);
    PERM(whh0, whh0r,         768,  256,  256, 1);
    PERM(wih1, wih1r,         768,  256,  256, 1);
    PERM(wfc,  wfcp,         VDIM,  256,  256, 0);
    prep_bcat<<<6, 256>>>(bih0, bhh1);
    zero_kernel<<<(BH + 255) / 256, 256>>>(h0, BH);
    zero_kernel<<<(BH + 255) / 256, 256>>>(hist, BH);

    // ---- encoder MLP (ROUND+perm outputs feed next GEMM) ----
    {
        GemmP p;
        p = { x,    w1r, b1, act0, 2048 };
        gemm_tc<true, true, true ><<<dim3(16, 64), 256, GSMEM_BYTES>>>(p, p, 99, FPDIM, 4860, 4864);
        p = { act0, w2r, b2, act1, 1024 };
        gemm_tc<true, true, false><<<dim3(8,  64), 256, GSMEM_BYTES>>>(p, p, 99, 2048, 2048, 2048);
        p = { act1, w3r, b3, act0, 512 };
        gemm_tc<true, true, false><<<dim3(4,  64), 256, GSMEM_BYTES>>>(p, p, 99, 1024, 1024, 1024);
        p = { act0, w4r, b4, act1, 256 };
        gemm_tc<true, true, false><<<dim3(2,  64), 256, GSMEM_BYTES>>>(p, p, 99, 512,  512,  512);
    }
    const float* e = act1;   // (B, E) permuted + rounded

    // ---- GRU over T steps ----
    const int gatesBlocks = (BH / 8 + 255) / 256;

    for (int t = 0; t < TSTEPS; t++) {
        const float* h1prev = hist + (size_t)t * BH;
        float*       h1new  = hist + (size_t)(t + 1) * BH;

        if (t == 0) {
            // gi0 = e @ wih0^T (+bih0); gh1 = 0 @ whh1^T (+bhh1); gh0 = 0 @ whh0^T (+bhh0)
            GemmP pa = { e,       wcat,           g_bcat ? bcat : bcat, giA,       1536 };
            GemmP pb = { h1prev,  wcat + 768*256, bcat + 768,           giA + 768, 1536 };
            gemm_tc<false, false, false><<<dim3(12, 64), 256, GSMEM_BYTES>>>(pa, pb, 6, HDIM, 256, 256);
            GemmP pc = { h0, whh0r, bhh0, gh0, 768 };
            gemm_tc<false, false, false><<<dim3(6, 64), 256, GSMEM_BYTES>>>(pc, pc, 99, HDIM, 256, 256);
        } else {
            // fused: [gi0|gh1] = h1prev @ wcat^T ; gh0 = h0 @ whh0^T
            GemmP pa = { h1prev, wcat,  bcat, giA, 1536 };
            GemmP pb = { h0,     whh0r, bhh0, gh0, 768 };
            gemm_tc<false, false, false><<<dim3(18, 64), 256, GSMEM_BYTES>>>(pa, pb, 12, HDIM, 256, 256);
        }
        // h0_t
        gru_gates<<<gatesBlocks, 256>>>(giA, 1536, gh0, 768, h0, h0);
        // gi1 = h0_t @ wih1^T
        {
            GemmP p = { h0, wih1r, bih1, gi1, 768 };
            gemm_tc<false, false, false><<<dim3(6, 64), 256, GSMEM_BYTES>>>(p, p, 99, HDIM, 256, 256);
        }
        // h1_t
        gru_gates<<<gatesBlocks, 256>>>(gi1, 768, giA + 768, 1536, h1prev, h1new);
    }

    // ---- fused FC + ReLU + softmax ----
    const long long totalWarps = (long long)BATCH * TSTEPS;
    const int fcBlocks = (int)((totalWarps * 32 + 255) / 256);
    fc_softmax_kernel<<<fcBlocks, 256>>>(hist, wfcp, bfc, out);
}

// round 5
// speedup vs baseline: 3.2616x; 1.2517x over previous
#include <cuda_runtime.h>
#include <cuda_fp16.h>
#include <math.h>
#include <stdint.h>

#define BATCH   8192
#define FPDIM   4860
#define FPPAD   4864
#define EDIM    256
#define HDIM    256
#define VDIM    42
#define TSTEPS  128

// ---------------------------------------------------------------------------
// Static device scratch
// ---------------------------------------------------------------------------
__device__ __half g_x16  [(size_t)BATCH * FPPAD];            // 80 MB
__device__ __half g_w1h  [(size_t)2048 * FPPAD];
__device__ __half g_w2h  [(size_t)1024 * 2048];
__device__ __half g_w3h  [(size_t)512 * 1024];
__device__ __half g_w4h  [(size_t)256 * 512];
__device__ __half g_wcath[(size_t)1536 * 256];               // [wih0 ; whh1]
__device__ __half g_whh0h[(size_t)768 * 256];
__device__ __half g_wih1h[(size_t)768 * 256];
__device__ float  g_bcat [1536];

__device__ __half g_act0h[(size_t)BATCH * 2048];
__device__ __half g_act1h[(size_t)BATCH * 1024];
__device__ __half g_e    [(size_t)BATCH * EDIM];
__device__ __half g_h0   [(size_t)BATCH * HDIM];
__device__ float  g_giA  [(size_t)BATCH * 1536];             // (gi0 | gh1)
__device__ float  g_gh0  [(size_t)BATCH * 768];
__device__ float  g_gi1  [(size_t)BATCH * 768];
__device__ __half g_hist [(size_t)(TSTEPS + 1) * BATCH * HDIM];  // 540 MB

// ---------------------------------------------------------------------------
// helpers
// ---------------------------------------------------------------------------
__device__ __forceinline__ uint32_t smem_u32(const void* p) {
    return (uint32_t)__cvta_generic_to_shared(p);
}
__device__ __forceinline__ void cp_async16(uint32_t dst, const void* src) {
    asm volatile("cp.async.cg.shared.global [%0], [%1], 16;\n"
                 :: "r"(dst), "l"(src));
}
#define CP_COMMIT()  asm volatile("cp.async.commit_group;\n")
#define CP_WAIT1()   asm volatile("cp.async.wait_group 1;\n")

__device__ __forceinline__ void ldm4(uint32_t addr, uint32_t& r0, uint32_t& r1,
                                     uint32_t& r2, uint32_t& r3) {
    asm volatile("ldmatrix.sync.aligned.m8n8.x4.shared.b16 {%0,%1,%2,%3}, [%4];"
                 : "=r"(r0), "=r"(r1), "=r"(r2), "=r"(r3) : "r"(addr));
}
__device__ __forceinline__ void mma16816(float c[4], const uint32_t a[4],
                                         uint32_t b0, uint32_t b1) {
    asm volatile("mma.sync.aligned.m16n8k16.row.col.f32.f16.f16.f32 "
                 "{%0,%1,%2,%3}, {%4,%5,%6,%7}, {%8,%9}, {%0,%1,%2,%3};"
                 : "+f"(c[0]), "+f"(c[1]), "+f"(c[2]), "+f"(c[3])
                 : "r"(a[0]), "r"(a[1]), "r"(a[2]), "r"(a[3]),
                   "r"(b0), "r"(b1));
}

// ---------------------------------------------------------------------------
// FP16 tensor GEMM:  C[M,N] = A[M,K] @ W[N,K]^T + bias[N]
// CTA 128x128, warp tile 64x32 (2x4 warps), BK=64, 2-stage cp.async,
// ldmatrix.x4 fragment loads, padded pitch 72 halves (conflict-free).
// Requirements: M,N multiples of 128; K multiple of 64. Holds at all call sites.
// Supports 2 fused problems split along grid.x.
// ---------------------------------------------------------------------------
#define PITCH   72                       // halves per smem row
#define ROWB    144                      // bytes per smem row
#define STG_H   (128 * PITCH)            // halves per tile per stage
#define STG_B   (STG_H * 2)              // 18 KB
#define SMEM_TOT (4 * STG_B)             // 73728 B

struct GemmP { const __half* A; const __half* W; const float* bias; void* C; int ldc; };

template<bool RELU, bool HOUT>
__global__ void __launch_bounds__(256, 2)
hgemm(GemmP p0, GemmP p1, int split, int lda, int K)
{
    extern __shared__ __half sh[];
    const uint32_t sbase = smem_u32(sh);

    const int tid  = threadIdx.x;
    int bxx = blockIdx.x;
    GemmP P = p0;
    if (bxx >= split) { P = p1; bxx -= split; }
    const int bm = blockIdx.y * 128;
    const int bn = bxx * 128;

    const int w    = tid >> 5;
    const int lane = tid & 31;
    const int wm   = (w & 1) * 64;       // 2 warps in M
    const int wn   = (w >> 1) * 32;      // 4 warps in N
    const int g    = lane >> 2;
    const int tg   = lane & 3;

    float acc[4][4][4];
    #pragma unroll
    for (int i = 0; i < 4; i++)
        #pragma unroll
        for (int j = 0; j < 4; j++)
            #pragma unroll
            for (int q = 0; q < 4; q++) acc[i][j][q] = 0.f;

    const int KT = K >> 6;               // K / 64
    const __half* A = P.A;
    const __half* W = P.W;

    // loader mapping: 8 chunks(16B)/row; thread t -> row (t>>3)+32i, chunk t&7
    const int lrow = tid >> 3;
    const int lc   = tid & 7;

    auto issue = [&](int kt, int st) {
        const uint32_t aB = sbase + st * 2 * STG_B;
        const uint32_t bB = aB + STG_B;
        const int koff = kt * 64 + lc * 8;
        #pragma unroll
        for (int i = 0; i < 4; i++) {
            const int r = lrow + i * 32;
            cp_async16(aB + r * ROWB + lc * 16, A + (size_t)(bm + r) * lda + koff);
            cp_async16(bB + r * ROWB + lc * 16, W + (size_t)(bn + r) * K   + koff);
        }
        CP_COMMIT();
    };

    // ldmatrix per-lane offsets
    const uint32_t aoff = (uint32_t)((wm + (lane & 15)) * ROWB + ((lane >> 4) << 4));
    const uint32_t boff = (uint32_t)((wn + ((lane >> 4) << 3) + (lane & 7)) * ROWB
                                     + (((lane >> 3) & 1) << 4));

    issue(0, 0);

    for (int kt = 0; kt < KT; kt++) {
        if (kt + 1 < KT) issue(kt + 1, (kt + 1) & 1);
        else             CP_COMMIT();
        CP_WAIT1();
        __syncthreads();

        const uint32_t aS = sbase + (kt & 1) * 2 * STG_B + aoff;
        const uint32_t bS = sbase + (kt & 1) * 2 * STG_B + STG_B + boff;

        #pragma unroll
        for (int s = 0; s < 4; s++) {                 // k16 steps within BK=64
            uint32_t a[4][4], b[2][4];
            #pragma unroll
            for (int i = 0; i < 4; i++)
                ldm4(aS + (uint32_t)(i * 16 * ROWB + s * 32),
                     a[i][0], a[i][1], a[i][2], a[i][3]);
            #pragma unroll
            for (int j2 = 0; j2 < 2; j2++)
                ldm4(bS + (uint32_t)(j2 * 16 * ROWB + s * 32),
                     b[j2][0], b[j2][1], b[j2][2], b[j2][3]);
            #pragma unroll
            for (int i = 0; i < 4; i++)
                #pragma unroll
                for (int j = 0; j < 4; j++)
                    mma16816(acc[i][j], a[i], b[j >> 1][(j & 1) * 2],
                             b[j >> 1][(j & 1) * 2 + 1]);
        }
        __syncthreads();
    }

    const float* bias = P.bias;
    const int ldc = P.ldc;

    float bx[4], by[4];
    #pragma unroll
    for (int j = 0; j < 4; j++) {
        const int n = bn + wn + j * 8 + 2 * tg;
        bx[j] = bias[n]; by[j] = bias[n + 1];
    }

    if (HOUT) {
        __half* C = (__half*)P.C;
        #pragma unroll
        for (int i = 0; i < 4; i++) {
            const int r0 = bm + wm + i * 16 + g;
            #pragma unroll
            for (int j = 0; j < 4; j++) {
                const int n = bn + wn + j * 8 + 2 * tg;
                float u0 = acc[i][j][0] + bx[j], u1 = acc[i][j][1] + by[j];
                float u2 = acc[i][j][2] + bx[j], u3 = acc[i][j][3] + by[j];
                if (RELU) {
                    u0 = fmaxf(u0, 0.f); u1 = fmaxf(u1, 0.f);
                    u2 = fmaxf(u2, 0.f); u3 = fmaxf(u3, 0.f);
                }
                *(__half2*)&C[(size_t)r0       * ldc + n] = __floats2half2_rn(u0, u1);
                *(__half2*)&C[(size_t)(r0 + 8) * ldc + n] = __floats2half2_rn(u2, u3);
            }
        }
    } else {
        float* C = (float*)P.C;
        #pragma unroll
        for (int i = 0; i < 4; i++) {
            const int r0 = bm + wm + i * 16 + g;
            #pragma unroll
            for (int j = 0; j < 4; j++) {
                const int n = bn + wn + j * 8 + 2 * tg;
                float2 v0, v1;
                v0.x = acc[i][j][0] + bx[j]; v0.y = acc[i][j][1] + by[j];
                v1.x = acc[i][j][2] + bx[j]; v1.y = acc[i][j][3] + by[j];
                if (RELU) {
                    v0.x = fmaxf(v0.x, 0.f); v0.y = fmaxf(v0.y, 0.f);
                    v1.x = fmaxf(v1.x, 0.f); v1.y = fmaxf(v1.y, 0.f);
                }
                *(float2*)&C[(size_t)r0       * ldc + n] = v0;
                *(float2*)&C[(size_t)(r0 + 8) * ldc + n] = v1;
            }
        }
    }
}

// ---------------------------------------------------------------------------
// GRU gates: 8 elements/thread. gi/gh fp32; hprev/hnew fp16 (natural layout).
// ---------------------------------------------------------------------------
__device__ __forceinline__ float sig_(float x)  { return 1.f / (1.f + __expf(-x)); }
__device__ __forceinline__ float tanh_(float x) { float e = __expf(2.f * x); return 1.f - 2.f / (e + 1.f); }

__global__ void gru_gates(const float* __restrict__ gi, int ldi,
                          const float* __restrict__ gh, int ldh,
                          const __half* __restrict__ hprev,
                          __half* __restrict__ hnew)
{
    const int idx = blockIdx.x * blockDim.x + threadIdx.x;
    if (idx >= BATCH * HDIM / 8) return;
    const int b = idx >> 5;
    const int q = (idx & 31) * 8;

    const float* gib = gi + (size_t)b * ldi + q;
    const float* ghb = gh + (size_t)b * ldh + q;

    float ir[8], iz[8], in_[8], hr[8], hz[8], hn[8];
    *(float4*)&ir[0]  = *(const float4*)(gib);
    *(float4*)&ir[4]  = *(const float4*)(gib + 4);
    *(float4*)&iz[0]  = *(const float4*)(gib + 256);
    *(float4*)&iz[4]  = *(const float4*)(gib + 260);
    *(float4*)&in_[0] = *(const float4*)(gib + 512);
    *(float4*)&in_[4] = *(const float4*)(gib + 516);
    *(float4*)&hr[0]  = *(const float4*)(ghb);
    *(float4*)&hr[4]  = *(const float4*)(ghb + 4);
    *(float4*)&hz[0]  = *(const float4*)(ghb + 256);
    *(float4*)&hz[4]  = *(const float4*)(ghb + 260);
    *(float4*)&hn[0]  = *(const float4*)(ghb + 512);
    *(float4*)&hn[4]  = *(const float4*)(ghb + 516);

    uint4 hv = *(const uint4*)(hprev + (size_t)b * HDIM + q);
    const __half2* hh = (const __half2*)&hv;
    float hpl[8];
    #pragma unroll
    for (int m = 0; m < 4; m++) {
        const float2 f = __half22float2(hh[m]);
        hpl[2 * m] = f.x; hpl[2 * m + 1] = f.y;
    }

    __half2 o[4];
    #pragma unroll
    for (int m = 0; m < 4; m++) {
        float ho[2];
        #pragma unroll
        for (int u = 0; u < 2; u++) {
            const int k = 2 * m + u;
            const float r = sig_(ir[k] + hr[k]);
            const float z = sig_(iz[k] + hz[k]);
            const float n = tanh_(in_[k] + r * hn[k]);
            ho[u] = (1.f - z) * n + z * hpl[k];
        }
        o[m] = __floats2half2_rn(ho[0], ho[1]);
    }
    *(uint4*)(hnew + (size_t)b * HDIM + q) = *(uint4*)o;
}

// ---------------------------------------------------------------------------
// prep kernels
// ---------------------------------------------------------------------------
__global__ void conv16(const float* __restrict__ src, __half* __restrict__ dst,
                       int N, int K, int Kpad)
{
    const int idx = blockIdx.x * blockDim.x + threadIdx.x;
    if (idx >= N * Kpad) return;
    const int row = idx / Kpad;
    const int k   = idx % Kpad;
    const float v = (k < K) ? src[(size_t)row * K + k] : 0.f;
    dst[idx] = __float2half_rn(v);
}

__global__ void prep_bcat(const float* __restrict__ bih0, const float* __restrict__ bhh1)
{
    const int idx = blockIdx.x * blockDim.x + threadIdx.x;
    if (idx < 768)       g_bcat[idx] = bih0[idx];
    else if (idx < 1536) g_bcat[idx] = bhh1[idx - 768];
}

__global__ void zero_h(__half* __restrict__ p, int n)   // n in half2 units
{
    const int idx = blockIdx.x * blockDim.x + threadIdx.x;
    if (idx < n) ((__half2*)p)[idx] = __floats2half2_rn(0.f, 0.f);
}

// ---------------------------------------------------------------------------
// Fused FC + ReLU + softmax (V=42), one warp per (b, t). hist fp16.
// ---------------------------------------------------------------------------
__global__ void __launch_bounds__(256)
fc_softmax_kernel(const __half* __restrict__ hist,
                  const float* __restrict__ wfc,
                  const float* __restrict__ bfc,
                  float* __restrict__ out)
{
    const int gwarp = (blockIdx.x * blockDim.x + threadIdx.x) >> 5;
    const int lane  = threadIdx.x & 31;
    const int wl    = threadIdx.x >> 5;
    if (gwarp >= BATCH * TSTEPS) return;
    const int b = gwarp / TSTEPS;
    const int t = gwarp % TSTEPS;

    __shared__ float hs[8][HDIM];
    const __half* h = hist + ((size_t)(t + 1) * BATCH + b) * HDIM;
    #pragma unroll
    for (int k = 0; k < HDIM / 64; k++) {
        const __half2 hv = *(const __half2*)&h[2 * (lane + k * 32)];
        const float2 f = __half22float2(hv);
        hs[wl][2 * (lane + k * 32)]     = f.x;
        hs[wl][2 * (lane + k * 32) + 1] = f.y;
    }
    __syncwarp();

    const float* hrow = hs[wl];
    const bool has2 = (lane < VDIM - 32);

    float v0 = bfc[lane];
    {
        const float4* w4 = (const float4*)&wfc[(size_t)lane * HDIM];
        float a = 0.f;
        #pragma unroll 8
        for (int k = 0; k < HDIM / 4; k++) {
            const float4 wv = w4[k];
            const float4 hv = *(const float4*)&hrow[k * 4];
            a += wv.x * hv.x + wv.y * hv.y + wv.z * hv.z + wv.w * hv.w;
        }
        v0 += a;
    }
    float v1 = -1e30f;
    if (has2) {
        v1 = bfc[lane + 32];
        const float4* w4 = (const float4*)&wfc[(size_t)(lane + 32) * HDIM];
        float a = 0.f;
        #pragma unroll 8
        for (int k = 0; k < HDIM / 4; k++) {
            const float4 wv = w4[k];
            const float4 hv = *(const float4*)&hrow[k * 4];
            a += wv.x * hv.x + wv.y * hv.y + wv.z * hv.z + wv.w * hv.w;
        }
        v1 += a;
    }

    v0 = fmaxf(v0, 0.f);
    const float lv1 = has2 ? fmaxf(v1, 0.f) : -1e30f;

    float m = fmaxf(v0, lv1);
    #pragma unroll
    for (int off = 16; off; off >>= 1) m = fmaxf(m, __shfl_xor_sync(0xffffffffu, m, off));

    const float e0 = expf(v0 - m);
    const float e1 = has2 ? expf(lv1 - m) : 0.f;
    float s = e0 + e1;
    #pragma unroll
    for (int off = 16; off; off >>= 1) s += __shfl_xor_sync(0xffffffffu, s, off);

    const float inv = 1.f / s;
    float* o = out + (size_t)gwarp * VDIM;
    o[lane] = e0 * inv;
    if (has2) o[lane + 32] = e1 * inv;
}

// ---------------------------------------------------------------------------
// Launch
// ---------------------------------------------------------------------------
extern "C" void kernel_launch(void* const* d_in, const int* in_sizes, int n_in,
                              void* d_out, int out_size)
{
    const float* x    = (const float*)d_in[0];
    const float* w1   = (const float*)d_in[1];
    const float* b1   = (const float*)d_in[2];
    const float* w2   = (const float*)d_in[3];
    const float* b2   = (const float*)d_in[4];
    const float* w3   = (const float*)d_in[5];
    const float* b3   = (const float*)d_in[6];
    const float* w4   = (const float*)d_in[7];
    const float* b4   = (const float*)d_in[8];
    const float* wih0 = (const float*)d_in[9];
    const float* whh0 = (const float*)d_in[10];
    const float* bih0 = (const float*)d_in[11];
    const float* bhh0 = (const float*)d_in[12];
    const float* wih1 = (const float*)d_in[13];
    const float* whh1 = (const float*)d_in[14];
    const float* bih1 = (const float*)d_in[15];
    const float* bhh1 = (const float*)d_in[16];
    const float* wfc  = (const float*)d_in[17];
    const float* bfc  = (const float*)d_in[18];
    float* out = (float*)d_out;

    __half *x16, *w1h, *w2h, *w3h, *w4h, *wcath, *whh0h, *wih1h;
    __half *act0h, *act1h, *e, *h0, *hist;
    float  *giA, *gh0, *gi1, *bcat;
    cudaGetSymbolAddress((void**)&x16,   g_x16);
    cudaGetSymbolAddress((void**)&w1h,   g_w1h);
    cudaGetSymbolAddress((void**)&w2h,   g_w2h);
    cudaGetSymbolAddress((void**)&w3h,   g_w3h);
    cudaGetSymbolAddress((void**)&w4h,   g_w4h);
    cudaGetSymbolAddress((void**)&wcath, g_wcath);
    cudaGetSymbolAddress((void**)&whh0h, g_whh0h);
    cudaGetSymbolAddress((void**)&wih1h, g_wih1h);
    cudaGetSymbolAddress((void**)&act0h, g_act0h);
    cudaGetSymbolAddress((void**)&act1h, g_act1h);
    cudaGetSymbolAddress((void**)&e,     g_e);
    cudaGetSymbolAddress((void**)&h0,    g_h0);
    cudaGetSymbolAddress((void**)&hist,  g_hist);
    cudaGetSymbolAddress((void**)&giA,   g_giA);
    cudaGetSymbolAddress((void**)&gh0,   g_gh0);
    cudaGetSymbolAddress((void**)&gi1,   g_gi1);
    cudaGetSymbolAddress((void**)&bcat,  g_bcat);

    static bool attr_set = false;
    if (!attr_set) {
        cudaFuncSetAttribute(hgemm<true,  true >, cudaFuncAttributeMaxDynamicSharedMemorySize, SMEM_TOT);
        cudaFuncSetAttribute(hgemm<false, false>, cudaFuncAttributeMaxDynamicSharedMemorySize, SMEM_TOT);
        attr_set = true;
    }

    const int BH = BATCH * HDIM;

    // ---- prep: fp32 -> fp16 conversions (deterministic, replayed) ----
    #define CONV(src, dst, N, K, Kp) \
        conv16<<<(int)(((size_t)(N) * (Kp) + 255) / 256), 256>>>(src, dst, N, K, Kp)
    CONV(x,    x16,   BATCH, FPDIM, FPPAD);
    CONV(w1,   w1h,   2048,  FPDIM, FPPAD);
    CONV(w2,   w2h,   1024,  2048,  2048);
    CONV(w3,   w3h,   512,   1024,  1024);
    CONV(w4,   w4h,   256,   512,   512);
    CONV(wih0, wcath, 768,   256,   256);
    CONV(whh1, wcath + (size_t)768 * 256, 768, 256, 256);
    CONV(whh0, whh0h, 768,   256,   256);
    CONV(wih1, wih1h, 768,   256,   256);
    prep_bcat<<<6, 256>>>(bih0, bhh1);
    zero_h<<<(BH / 2 + 255) / 256, 256>>>(h0, BH / 2);
    zero_h<<<(BH / 2 + 255) / 256, 256>>>(hist, BH / 2);

    // ---- encoder MLP (fp16 activations) ----
    {
        GemmP p;
        p = { x16,   w1h, b1, act0h, 2048 };
        hgemm<true, true><<<dim3(16, 64), 256, SMEM_TOT>>>(p, p, 99, FPPAD, FPPAD);
        p = { act0h, w2h, b2, act1h, 1024 };
        hgemm<true, true><<<dim3(8,  64), 256, SMEM_TOT>>>(p, p, 99, 2048, 2048);
        p = { act1h, w3h, b3, act0h, 512 };
        hgemm<true, true><<<dim3(4,  64), 256, SMEM_TOT>>>(p, p, 99, 1024, 1024);
        p = { act0h, w4h, b4, e, 256 };
        hgemm<true, true><<<dim3(2,  64), 256, SMEM_TOT>>>(p, p, 99, 512, 512);
    }

    // ---- GRU over T steps ----
    const int gatesBlocks = (BH / 8 + 255) / 256;

    for (int t = 0; t < TSTEPS; t++) {
        const __half* h1prev = hist + (size_t)t * BH;
        __half*       h1new  = hist + (size_t)(t + 1) * BH;

        if (t == 0) {
            GemmP pa = { e,       wcath,                     bcat,       giA,       1536 };
            GemmP pb = { h1prev,  wcath + (size_t)768 * 256, bcat + 768, giA + 768, 1536 };
            hgemm<false, false><<<dim3(12, 64), 256, SMEM_TOT>>>(pa, pb, 6, HDIM, 256);
            GemmP pc = { h0, whh0h, bhh0, gh0, 768 };
            hgemm<false, false><<<dim3(6, 64), 256, SMEM_TOT>>>(pc, pc, 99, HDIM, 256);
        } else {
            GemmP pa = { h1prev, wcath, bcat, giA, 1536 };
            GemmP pb = { h0,     whh0h, bhh0, gh0, 768 };
            hgemm<false, false><<<dim3(18, 64), 256, SMEM_TOT>>>(pa, pb, 12, HDIM, 256);
        }
        gru_gates<<<gatesBlocks, 256>>>(giA, 1536, gh0, 768, h0, h0);
        {
            GemmP p = { h0, wih1h, bih1, gi1, 768 };
            hgemm<false, false><<<dim3(6, 64), 256, SMEM_TOT>>>(p, p, 99, HDIM, 256);
        }
        gru_gates<<<gatesBlocks, 256>>>(gi1, 768, giA + 768, 1536, h1prev, h1new);
    }

    // ---- fused FC + ReLU + softmax ----
    const long long totalWarps = (long long)BATCH * TSTEPS;
    const int fcBlocks = (int)((totalWarps * 32 + 255) / 256);
    fc_softmax_kernel<<<fcBlocks, 256>>>(hist, wfc, bfc, out);
}

// round 6
// speedup vs baseline: 3.4474x; 1.0570x over previous
#include <cuda_runtime.h>
#include <cuda_fp16.h>
#include <math.h>
#include <stdint.h>

#define BATCH   8192
#define FPDIM   4860
#define FPPAD   4864
#define EDIM    256
#define HDIM    256
#define VDIM    42
#define TSTEPS  128

// ---------------------------------------------------------------------------
// Static device scratch
// ---------------------------------------------------------------------------
__device__ __half g_x16  [(size_t)BATCH * FPPAD];
__device__ __half g_w1h  [(size_t)2048 * FPPAD];
__device__ __half g_w2h  [(size_t)1024 * 2048];
__device__ __half g_w3h  [(size_t)512 * 1024];
__device__ __half g_w4h  [(size_t)256 * 512];
__device__ __half g_wcath[(size_t)1536 * 256];               // [wih0 ; whh1]
__device__ __half g_whh0h[(size_t)768 * 256];
__device__ __half g_wih1h[(size_t)768 * 256];
__device__ float  g_bcat [1536];

__device__ __half g_act0h[(size_t)BATCH * 2048];
__device__ __half g_act1h[(size_t)BATCH * 1024];
__device__ __half g_e    [(size_t)BATCH * EDIM];
__device__ __half g_h0   [(size_t)BATCH * HDIM];
__device__ __half g_giA  [(size_t)BATCH * 1536];             // (gi0 | gh1), fp16
__device__ __half g_gh0  [(size_t)BATCH * 768];
__device__ __half g_gi1  [(size_t)BATCH * 768];
__device__ __half g_hist [(size_t)(TSTEPS + 1) * BATCH * HDIM];

// ---------------------------------------------------------------------------
// helpers
// ---------------------------------------------------------------------------
__device__ __forceinline__ uint32_t smem_u32(const void* p) {
    return (uint32_t)__cvta_generic_to_shared(p);
}
__device__ __forceinline__ void cp_async16(uint32_t dst, const void* src) {
    asm volatile("cp.async.cg.shared.global [%0], [%1], 16;\n"
                 :: "r"(dst), "l"(src));
}
#define CP_COMMIT()  asm volatile("cp.async.commit_group;\n")
#define CP_WAIT2()   asm volatile("cp.async.wait_group 2;\n")

#define SWZ(x) ((x) ^ (((x) >> 3) & 0x70))

__device__ __forceinline__ void ldm4(uint32_t addr, uint32_t& r0, uint32_t& r1,
                                     uint32_t& r2, uint32_t& r3) {
    asm volatile("ldmatrix.sync.aligned.m8n8.x4.shared.b16 {%0,%1,%2,%3}, [%4];"
                 : "=r"(r0), "=r"(r1), "=r"(r2), "=r"(r3) : "r"(addr));
}
__device__ __forceinline__ void mma16816(float c[4], const uint32_t a[4],
                                         uint32_t b0, uint32_t b1) {
    asm volatile("mma.sync.aligned.m16n8k16.row.col.f32.f16.f16.f32 "
                 "{%0,%1,%2,%3}, {%4,%5,%6,%7}, {%8,%9}, {%0,%1,%2,%3};"
                 : "+f"(c[0]), "+f"(c[1]), "+f"(c[2]), "+f"(c[3])
                 : "r"(a[0]), "r"(a[1]), "r"(a[2]), "r"(a[3]),
                   "r"(b0), "r"(b1));
}

// ---------------------------------------------------------------------------
// FP16 tensor GEMM:  C[M,N] = A[M,K] @ W[N,K]^T + bias[N] (+ReLU), fp16 out.
// CTA 128x128, 4 warps (2x2), warp tile 64x64, BK=64, 3-stage cp.async,
// SW128-swizzled smem (no padding), ldmatrix.x4 fragments.
// Requirements: M,N mult of 128; K mult of 64, K >= 192. Holds at all sites.
// Supports 2 fused problems split along grid.x.
// ---------------------------------------------------------------------------
#define NSTG     3
#define TILE_B   16384                    // 128 rows * 128B
#define STAGE_B  (2 * TILE_B)             // A + W
#define SMEM_TOT (NSTG * STAGE_B)         // 98304

struct GemmP { const __half* A; const __half* W; const float* bias; __half* C; int ldc; };

template<bool RELU>
__global__ void __launch_bounds__(128, 2)
hgemm(GemmP p0, GemmP p1, int split, int lda, int K)
{
    extern __shared__ __half sh[];
    const uint32_t sbase = smem_u32(sh);

    const int tid  = threadIdx.x;
    int bxx = blockIdx.x;
    GemmP P = p0;
    if (bxx >= split) { P = p1; bxx -= split; }
    const int bm = blockIdx.y * 128;
    const int bn = bxx * 128;

    const int w    = tid >> 5;
    const int lane = tid & 31;
    const int wm   = (w & 1) * 64;
    const int wn   = (w >> 1) * 64;
    const int g    = lane >> 2;
    const int tg   = lane & 3;

    float acc[4][8][4];
    #pragma unroll
    for (int i = 0; i < 4; i++)
        #pragma unroll
        for (int j = 0; j < 8; j++)
            #pragma unroll
            for (int q = 0; q < 4; q++) acc[i][j][q] = 0.f;

    const int KT = K >> 6;
    const __half* A = P.A;
    const __half* W = P.W;

    auto issue = [&](int kt) {
        const uint32_t st = sbase + (kt % NSTG) * STAGE_B;
        const int koff = kt * 64;
        #pragma unroll
        for (int i = 0; i < 8; i++) {
            const int c = i * 128 + tid;           // 0..1023
            const int row = c >> 3, col = c & 7;
            cp_async16(st + SWZ((row << 7) + (col << 4)),
                       A + (size_t)(bm + row) * lda + koff + col * 8);
        }
        #pragma unroll
        for (int i = 0; i < 8; i++) {
            const int c = i * 128 + tid;
            const int row = c >> 3, col = c & 7;
            cp_async16(st + TILE_B + SWZ((row << 7) + (col << 4)),
                       W + (size_t)(bn + row) * K + koff + col * 8);
        }
        CP_COMMIT();
    };

    issue(0); issue(1); issue(2);

    // per-lane fragment row/byte components (swizzle applied per use)
    const int arow = wm + (lane & 15);
    const int abyt = (lane >> 4) << 4;
    const int brow = wn + ((lane >> 4) << 3) + (lane & 7);
    const int bbyt = ((lane >> 3) & 1) << 4;

    for (int kt = 0; kt < KT; kt++) {
        CP_WAIT2();
        __syncthreads();

        const uint32_t st = sbase + (kt % NSTG) * STAGE_B;

        #pragma unroll
        for (int s = 0; s < 4; s++) {
            uint32_t a[4][4], b[4][4];
            #pragma unroll
            for (int i = 0; i < 4; i++)
                ldm4(st + SWZ(((arow + i * 16) << 7) + s * 32 + abyt),
                     a[i][0], a[i][1], a[i][2], a[i][3]);
            #pragma unroll
            for (int j2 = 0; j2 < 4; j2++)
                ldm4(st + TILE_B + SWZ(((brow + j2 * 16) << 7) + s * 32 + bbyt),
                     b[j2][0], b[j2][1], b[j2][2], b[j2][3]);
            #pragma unroll
            for (int i = 0; i < 4; i++)
                #pragma unroll
                for (int j = 0; j < 8; j++)
                    mma16816(acc[i][j], a[i],
                             b[j >> 1][(j & 1) * 2], b[j >> 1][(j & 1) * 2 + 1]);
        }
        __syncthreads();
        if (kt + NSTG < KT) issue(kt + NSTG);
        else                CP_COMMIT();
    }

    // ---- epilogue: bias (+ReLU), fp16 half2 stores ----
    const float* bias = P.bias;
    __half* C = P.C;
    const int ldc = P.ldc;

    float bx[8], by[8];
    #pragma unroll
    for (int j = 0; j < 8; j++) {
        const int n = bn + wn + j * 8 + 2 * tg;
        bx[j] = bias[n]; by[j] = bias[n + 1];
    }
    #pragma unroll
    for (int i = 0; i < 4; i++) {
        const int r0 = bm + wm + i * 16 + g;
        #pragma unroll
        for (int j = 0; j < 8; j++) {
            const int n = bn + wn + j * 8 + 2 * tg;
            float u0 = acc[i][j][0] + bx[j], u1 = acc[i][j][1] + by[j];
            float u2 = acc[i][j][2] + bx[j], u3 = acc[i][j][3] + by[j];
            if (RELU) {
                u0 = fmaxf(u0, 0.f); u1 = fmaxf(u1, 0.f);
                u2 = fmaxf(u2, 0.f); u3 = fmaxf(u3, 0.f);
            }
            *(__half2*)&C[(size_t)r0       * ldc + n] = __floats2half2_rn(u0, u1);
            *(__half2*)&C[(size_t)(r0 + 8) * ldc + n] = __floats2half2_rn(u2, u3);
        }
    }
}

// ---------------------------------------------------------------------------
// GRU gates: 8 elements/thread, all fp16 I/O, fp32 math.
// ---------------------------------------------------------------------------
__device__ __forceinline__ float sig_(float x)  { return 1.f / (1.f + __expf(-x)); }
__device__ __forceinline__ float tanh_(float x) { float e = __expf(2.f * x); return 1.f - 2.f / (e + 1.f); }

__device__ __forceinline__ void load8h(float* f, const __half* p) {
    const uint4 v = *(const uint4*)p;
    const __half2* h2 = (const __half2*)&v;
    #pragma unroll
    for (int m = 0; m < 4; m++) {
        const float2 t = __half22float2(h2[m]);
        f[2 * m] = t.x; f[2 * m + 1] = t.y;
    }
}

__global__ void gru_gates(const __half* __restrict__ gi, int ldi,
                          const __half* __restrict__ gh, int ldh,
                          const __half* __restrict__ hprev,
                          __half* __restrict__ hnew)
{
    const int idx = blockIdx.x * blockDim.x + threadIdx.x;
    if (idx >= BATCH * HDIM / 8) return;
    const int b = idx >> 5;
    const int q = (idx & 31) * 8;

    const __half* gib = gi + (size_t)b * ldi + q;
    const __half* ghb = gh + (size_t)b * ldh + q;

    float ir[8], iz[8], in_[8], hr[8], hz[8], hn[8], hpl[8];
    load8h(ir,  gib);
    load8h(iz,  gib + 256);
    load8h(in_, gib + 512);
    load8h(hr,  ghb);
    load8h(hz,  ghb + 256);
    load8h(hn,  ghb + 512);
    load8h(hpl, hprev + (size_t)b * HDIM + q);

    __half2 o[4];
    #pragma unroll
    for (int m = 0; m < 4; m++) {
        float ho[2];
        #pragma unroll
        for (int u = 0; u < 2; u++) {
            const int k = 2 * m + u;
            const float r = sig_(ir[k] + hr[k]);
            const float z = sig_(iz[k] + hz[k]);
            const float n = tanh_(in_[k] + r * hn[k]);
            ho[u] = (1.f - z) * n + z * hpl[k];
        }
        o[m] = __floats2half2_rn(ho[0], ho[1]);
    }
    *(uint4*)(hnew + (size_t)b * HDIM + q) = *(uint4*)o;
}

// ---------------------------------------------------------------------------
// prep kernels
// ---------------------------------------------------------------------------
__global__ void conv16(const float* __restrict__ src, __half* __restrict__ dst,
                       int N, int K, int Kpad)
{
    const int idx = blockIdx.x * blockDim.x + threadIdx.x;
    if (idx >= N * Kpad) return;
    const int row = idx / Kpad;
    const int k   = idx % Kpad;
    const float v = (k < K) ? src[(size_t)row * K + k] : 0.f;
    dst[idx] = __float2half_rn(v);
}

__global__ void prep_bcat(const float* __restrict__ bih0, const float* __restrict__ bhh1)
{
    const int idx = blockIdx.x * blockDim.x + threadIdx.x;
    if (idx < 768)       g_bcat[idx] = bih0[idx];
    else if (idx < 1536) g_bcat[idx] = bhh1[idx - 768];
}

__global__ void zero_h(__half* __restrict__ p, int n)   // n in half2 units
{
    const int idx = blockIdx.x * blockDim.x + threadIdx.x;
    if (idx < n) ((__half2*)p)[idx] = __floats2half2_rn(0.f, 0.f);
}

// ---------------------------------------------------------------------------
// Fused FC + ReLU + softmax (V=42), one warp per (b, t). hist fp16.
// ---------------------------------------------------------------------------
__global__ void __launch_bounds__(256)
fc_softmax_kernel(const __half* __restrict__ hist,
                  const float* __restrict__ wfc,
                  const float* __restrict__ bfc,
                  float* __restrict__ out)
{
    const int gwarp = (blockIdx.x * blockDim.x + threadIdx.x) >> 5;
    const int lane  = threadIdx.x & 31;
    const int wl    = threadIdx.x >> 5;
    if (gwarp >= BATCH * TSTEPS) return;
    const int b = gwarp / TSTEPS;
    const int t = gwarp % TSTEPS;

    __shared__ float hs[8][HDIM];
    const __half* h = hist + ((size_t)(t + 1) * BATCH + b) * HDIM;
    #pragma unroll
    for (int k = 0; k < HDIM / 64; k++) {
        const __half2 hv = *(const __half2*)&h[2 * (lane + k * 32)];
        const float2 f = __half22float2(hv);
        hs[wl][2 * (lane + k * 32)]     = f.x;
        hs[wl][2 * (lane + k * 32) + 1] = f.y;
    }
    __syncwarp();

    const float* hrow = hs[wl];
    const bool has2 = (lane < VDIM - 32);

    float v0 = bfc[lane];
    {
        const float4* w4 = (const float4*)&wfc[(size_t)lane * HDIM];
        float a = 0.f;
        #pragma unroll 8
        for (int k = 0; k < HDIM / 4; k++) {
            const float4 wv = w4[k];
            const float4 hv = *(const float4*)&hrow[k * 4];
            a += wv.x * hv.x + wv.y * hv.y + wv.z * hv.z + wv.w * hv.w;
        }
        v0 += a;
    }
    float v1 = -1e30f;
    if (has2) {
        v1 = bfc[lane + 32];
        const float4* w4 = (const float4*)&wfc[(size_t)(lane + 32) * HDIM];
        float a = 0.f;
        #pragma unroll 8
        for (int k = 0; k < HDIM / 4; k++) {
            const float4 wv = w4[k];
            const float4 hv = *(const float4*)&hrow[k * 4];
            a += wv.x * hv.x + wv.y * hv.y + wv.z * hv.z + wv.w * hv.w;
        }
        v1 += a;
    }

    v0 = fmaxf(v0, 0.f);
    const float lv1 = has2 ? fmaxf(v1, 0.f) : -1e30f;

    float m = fmaxf(v0, lv1);
    #pragma unroll
    for (int off = 16; off; off >>= 1) m = fmaxf(m, __shfl_xor_sync(0xffffffffu, m, off));

    const float e0 = expf(v0 - m);
    const float e1 = has2 ? expf(lv1 - m) : 0.f;
    float s = e0 + e1;
    #pragma unroll
    for (int off = 16; off; off >>= 1) s += __shfl_xor_sync(0xffffffffu, s, off);

    const float inv = 1.f / s;
    float* o = out + (size_t)gwarp * VDIM;
    o[lane] = e0 * inv;
    if (has2) o[lane + 32] = e1 * inv;
}

// ---------------------------------------------------------------------------
// Launch
// ---------------------------------------------------------------------------
extern "C" void kernel_launch(void* const* d_in, const int* in_sizes, int n_in,
                              void* d_out, int out_size)
{
    const float* x    = (const float*)d_in[0];
    const float* w1   = (const float*)d_in[1];
    const float* b1   = (const float*)d_in[2];
    const float* w2   = (const float*)d_in[3];
    const float* b2   = (const float*)d_in[4];
    const float* w3   = (const float*)d_in[5];
    const float* b3   = (const float*)d_in[6];
    const float* w4   = (const float*)d_in[7];
    const float* b4   = (const float*)d_in[8];
    const float* wih0 = (const float*)d_in[9];
    const float* whh0 = (const float*)d_in[10];
    const float* bih0 = (const float*)d_in[11];
    const float* bhh0 = (const float*)d_in[12];
    const float* wih1 = (const float*)d_in[13];
    const float* whh1 = (const float*)d_in[14];
    const float* bih1 = (const float*)d_in[15];
    const float* bhh1 = (const float*)d_in[16];
    const float* wfc  = (const float*)d_in[17];
    const float* bfc  = (const float*)d_in[18];
    float* out = (float*)d_out;

    __half *x16, *w1h, *w2h, *w3h, *w4h, *wcath, *whh0h, *wih1h;
    __half *act0h, *act1h, *e, *h0, *hist, *giA, *gh0, *gi1;
    float *bcat;
    cudaGetSymbolAddress((void**)&x16,   g_x16);
    cudaGetSymbolAddress((void**)&w1h,   g_w1h);
    cudaGetSymbolAddress((void**)&w2h,   g_w2h);
    cudaGetSymbolAddress((void**)&w3h,   g_w3h);
    cudaGetSymbolAddress((void**)&w4h,   g_w4h);
    cudaGetSymbolAddress((void**)&wcath, g_wcath);
    cudaGetSymbolAddress((void**)&whh0h, g_whh0h);
    cudaGetSymbolAddress((void**)&wih1h, g_wih1h);
    cudaGetSymbolAddress((void**)&act0h, g_act0h);
    cudaGetSymbolAddress((void**)&act1h, g_act1h);
    cudaGetSymbolAddress((void**)&e,     g_e);
    cudaGetSymbolAddress((void**)&h0,    g_h0);
    cudaGetSymbolAddress((void**)&hist,  g_hist);
    cudaGetSymbolAddress((void**)&giA,   g_giA);
    cudaGetSymbolAddress((void**)&gh0,   g_gh0);
    cudaGetSymbolAddress((void**)&gi1,   g_gi1);
    cudaGetSymbolAddress((void**)&bcat,  g_bcat);

    static bool attr_set = false;
    if (!attr_set) {
        cudaFuncSetAttribute(hgemm<true >, cudaFuncAttributeMaxDynamicSharedMemorySize, SMEM_TOT);
        cudaFuncSetAttribute(hgemm<false>, cudaFuncAttributeMaxDynamicSharedMemorySize, SMEM_TOT);
        attr_set = true;
    }

    const int BH = BATCH * HDIM;

    // ---- prep: fp32 -> fp16 conversions ----
    #define CONV(src, dst, N, K, Kp) \
        conv16<<<(int)(((size_t)(N) * (Kp) + 255) / 256), 256>>>(src, dst, N, K, Kp)
    CONV(x,    x16,   BATCH, FPDIM, FPPAD);
    CONV(w1,   w1h,   2048,  FPDIM, FPPAD);
    CONV(w2,   w2h,   1024,  2048,  2048);
    CONV(w3,   w3h,   512,   1024,  1024);
    CONV(w4,   w4h,   256,   512,   512);
    CONV(wih0, wcath, 768,   256,   256);
    CONV(whh1, wcath + (size_t)768 * 256, 768, 256, 256);
    CONV(whh0, whh0h, 768,   256,   256);
    CONV(wih1, wih1h, 768,   256,   256);
    prep_bcat<<<6, 256>>>(bih0, bhh1);
    zero_h<<<(BH / 2 + 255) / 256, 256>>>(h0, BH / 2);
    zero_h<<<(BH / 2 + 255) / 256, 256>>>(hist, BH / 2);

    // ---- encoder MLP (fp16 activations) ----
    {
        GemmP p;
        p = { x16,   w1h, b1, act0h, 2048 };
        hgemm<true><<<dim3(16, 64), 128, SMEM_TOT>>>(p, p, 99, FPPAD, FPPAD);
        p = { act0h, w2h, b2, act1h, 1024 };
        hgemm<true><<<dim3(8,  64), 128, SMEM_TOT>>>(p, p, 99, 2048, 2048);
        p = { act1h, w3h, b3, act0h, 512 };
        hgemm<true><<<dim3(4,  64), 128, SMEM_TOT>>>(p, p, 99, 1024, 1024);
        p = { act0h, w4h, b4, e, 256 };
        hgemm<true><<<dim3(2,  64), 128, SMEM_TOT>>>(p, p, 99, 512, 512);
    }

    // ---- GRU over T steps ----
    const int gatesBlocks = (BH / 8 + 255) / 256;

    for (int t = 0; t < TSTEPS; t++) {
        const __half* h1prev = hist + (size_t)t * BH;
        __half*       h1new  = hist + (size_t)(t + 1) * BH;

        if (t == 0) {
            GemmP pa = { e,       wcath,                     bcat,       giA,       1536 };
            GemmP pb = { h1prev,  wcath + (size_t)768 * 256, bcat + 768, giA + 768, 1536 };
            hgemm<false><<<dim3(12, 64), 128, SMEM_TOT>>>(pa, pb, 6, HDIM, 256);
            GemmP pc = { h0, whh0h, bhh0, gh0, 768 };
            hgemm<false><<<dim3(6, 64), 128, SMEM_TOT>>>(pc, pc, 99, HDIM, 256);
        } else {
            GemmP pa = { h1prev, wcath, bcat, giA, 1536 };
            GemmP pb = { h0,     whh0h, bhh0, gh0, 768 };
            hgemm<false><<<dim3(18, 64), 128, SMEM_TOT>>>(pa, pb, 12, HDIM, 256);
        }
        gru_gates<<<gatesBlocks, 256>>>(giA, 1536, gh0, 768, h0, h0);
        {
            GemmP p = { h0, wih1h, bih1, gi1, 768 };
            hgemm<false><<<dim3(6, 64), 128, SMEM_TOT>>>(p, p, 99, HDIM, 256);
        }
        gru_gates<<<gatesBlocks, 256>>>(gi1, 768, giA + 768, 1536, h1prev, h1new);
    }

    // ---- fused FC + ReLU + softmax ----
    const long long totalWarps = (long long)BATCH * TSTEPS;
    const int fcBlocks = (int)((totalWarps * 32 + 255) / 256);
    fc_softmax_kernel<<<fcBlocks, 256>>>(hist, wfc, bfc, out);
}

// round 7
// speedup vs baseline: 3.4502x; 1.0008x over previous
#include <cuda_runtime.h>
#include <cuda_fp16.h>
#include <math.h>
#include <stdint.h>

#define BATCH   8192
#define FPDIM   4860
#define FPPAD   4864
#define EDIM    256
#define HDIM    256
#define VDIM    42
#define TSTEPS  128

// ---------------------------------------------------------------------------
// Static device scratch
// ---------------------------------------------------------------------------
__device__ __half g_x16  [(size_t)BATCH * FPPAD];
__device__ __half g_w1h  [(size_t)2048 * FPPAD];
__device__ __half g_w2h  [(size_t)1024 * 2048];
__device__ __half g_w3h  [(size_t)512 * 1024];
__device__ __half g_w4h  [(size_t)256 * 512];
__device__ __half g_wcath[(size_t)1536 * 256];               // [wih0 ; whh1]
__device__ __half g_whh0h[(size_t)768 * 256];
__device__ __half g_wih1h[(size_t)768 * 256];
__device__ float  g_bcat [1536];

__device__ __half g_act0h[(size_t)BATCH * 2048];
__device__ __half g_act1h[(size_t)BATCH * 1024];
__device__ __half g_e    [(size_t)BATCH * EDIM];
__device__ __half g_h0   [(size_t)BATCH * HDIM];
__device__ __half g_giA  [(size_t)BATCH * 1536];             // (gi0 | gh1), fp16
__device__ __half g_gh0  [(size_t)BATCH * 768];
__device__ __half g_gi1  [(size_t)BATCH * 768];
__device__ __half g_hist [(size_t)(TSTEPS + 1) * BATCH * HDIM];

// ---------------------------------------------------------------------------
// helpers
// ---------------------------------------------------------------------------
__device__ __forceinline__ uint32_t smem_u32(const void* p) {
    return (uint32_t)__cvta_generic_to_shared(p);
}
__device__ __forceinline__ void cp_async16(uint32_t dst, const void* src) {
    asm volatile("cp.async.cg.shared.global [%0], [%1], 16;\n"
                 :: "r"(dst), "l"(src));
}
#define CP_COMMIT()  asm volatile("cp.async.commit_group;\n")
#define CP_WAIT2()   asm volatile("cp.async.wait_group 2;\n")

#define SWZ(x) ((x) ^ (((x) >> 3) & 0x70))

__device__ __forceinline__ void ldm4(uint32_t addr, uint32_t& r0, uint32_t& r1,
                                     uint32_t& r2, uint32_t& r3) {
    asm volatile("ldmatrix.sync.aligned.m8n8.x4.shared.b16 {%0,%1,%2,%3}, [%4];"
                 : "=r"(r0), "=r"(r1), "=r"(r2), "=r"(r3) : "r"(addr));
}
__device__ __forceinline__ void mma16816(float c[4], const uint32_t a[4],
                                         uint32_t b0, uint32_t b1) {
    asm volatile("mma.sync.aligned.m16n8k16.row.col.f32.f16.f16.f32 "
                 "{%0,%1,%2,%3}, {%4,%5,%6,%7}, {%8,%9}, {%0,%1,%2,%3};"
                 : "+f"(c[0]), "+f"(c[1]), "+f"(c[2]), "+f"(c[3])
                 : "r"(a[0]), "r"(a[1]), "r"(a[2]), "r"(a[3]),
                   "r"(b0), "r"(b1));
}

// ---------------------------------------------------------------------------
// FP16 tensor GEMM:  C[M,N] = A[M,K] @ W[N,K]^T + bias[N] (+ReLU), fp16 out.
// CTA 128x128, 4 warps (2x2), warp tile 64x64, BK=64, 3-stage cp.async,
// SW128-swizzled smem (no padding), ldmatrix.x4 fragments.
// Requirements: M,N mult of 128; K mult of 64, K >= 192. Holds at all sites.
// Supports 2 fused problems split along grid.x.
// ---------------------------------------------------------------------------
#define NSTG     3
#define TILE_B   16384                    // 128 rows * 128B
#define STAGE_B  (2 * TILE_B)             // A + W
#define SMEM_TOT (NSTG * STAGE_B)         // 98304

struct GemmP { const __half* A; const __half* W; const float* bias; __half* C; int ldc; };

template<bool RELU>
__global__ void __launch_bounds__(128, 2)
hgemm(GemmP p0, GemmP p1, int split, int lda, int K)
{
    extern __shared__ __half sh[];
    const uint32_t sbase = smem_u32(sh);

    const int tid  = threadIdx.x;
    int bxx = blockIdx.x;
    GemmP P = p0;
    if (bxx >= split) { P = p1; bxx -= split; }
    const int bm = blockIdx.y * 128;
    const int bn = bxx * 128;

    const int w    = tid >> 5;
    const int lane = tid & 31;
    const int wm   = (w & 1) * 64;
    const int wn   = (w >> 1) * 64;
    const int g    = lane >> 2;
    const int tg   = lane & 3;

    float acc[4][8][4];
    #pragma unroll
    for (int i = 0; i < 4; i++)
        #pragma unroll
        for (int j = 0; j < 8; j++)
            #pragma unroll
            for (int q = 0; q < 4; q++) acc[i][j][q] = 0.f;

    const int KT = K >> 6;
    const __half* A = P.A;
    const __half* W = P.W;

    auto issue = [&](int kt) {
        const uint32_t st = sbase + (kt % NSTG) * STAGE_B;
        const int koff = kt * 64;
        #pragma unroll
        for (int i = 0; i < 8; i++) {
            const int c = i * 128 + tid;           // 0..1023
            const int row = c >> 3, col = c & 7;
            cp_async16(st + SWZ((row << 7) + (col << 4)),
                       A + (size_t)(bm + row) * lda + koff + col * 8);
        }
        #pragma unroll
        for (int i = 0; i < 8; i++) {
            const int c = i * 128 + tid;
            const int row = c >> 3, col = c & 7;
            cp_async16(st + TILE_B + SWZ((row << 7) + (col << 4)),
                       W + (size_t)(bn + row) * K + koff + col * 8);
        }
        CP_COMMIT();
    };

    issue(0); issue(1); issue(2);

    // per-lane fragment row/byte components (swizzle applied per use)
    const int arow = wm + (lane & 15);
    const int abyt = (lane >> 4) << 4;
    const int brow = wn + ((lane >> 4) << 3) + (lane & 7);
    const int bbyt = ((lane >> 3) & 1) << 4;

    for (int kt = 0; kt < KT; kt++) {
        CP_WAIT2();
        __syncthreads();

        const uint32_t st = sbase + (kt % NSTG) * STAGE_B;

        #pragma unroll
        for (int s = 0; s < 4; s++) {
            uint32_t a[4][4], b[4][4];
            #pragma unroll
            for (int i = 0; i < 4; i++)
                ldm4(st + SWZ(((arow + i * 16) << 7) + s * 32 + abyt),
                     a[i][0], a[i][1], a[i][2], a[i][3]);
            #pragma unroll
            for (int j2 = 0; j2 < 4; j2++)
                ldm4(st + TILE_B + SWZ(((brow + j2 * 16) << 7) + s * 32 + bbyt),
                     b[j2][0], b[j2][1], b[j2][2], b[j2][3]);
            #pragma unroll
            for (int i = 0; i < 4; i++)
                #pragma unroll
                for (int j = 0; j < 8; j++)
                    mma16816(acc[i][j], a[i],
                             b[j >> 1][(j & 1) * 2], b[j >> 1][(j & 1) * 2 + 1]);
        }
        __syncthreads();
        if (kt + NSTG < KT) issue(kt + NSTG);
        else                CP_COMMIT();
    }

    // ---- epilogue: bias (+ReLU), fp16 half2 stores ----
    const float* bias = P.bias;
    __half* C = P.C;
    const int ldc = P.ldc;

    float bx[8], by[8];
    #pragma unroll
    for (int j = 0; j < 8; j++) {
        const int n = bn + wn + j * 8 + 2 * tg;
        bx[j] = bias[n]; by[j] = bias[n + 1];
    }
    #pragma unroll
    for (int i = 0; i < 4; i++) {
        const int r0 = bm + wm + i * 16 + g;
        #pragma unroll
        for (int j = 0; j < 8; j++) {
            const int n = bn + wn + j * 8 + 2 * tg;
            float u0 = acc[i][j][0] + bx[j], u1 = acc[i][j][1] + by[j];
            float u2 = acc[i][j][2] + bx[j], u3 = acc[i][j][3] + by[j];
            if (RELU) {
                u0 = fmaxf(u0, 0.f); u1 = fmaxf(u1, 0.f);
                u2 = fmaxf(u2, 0.f); u3 = fmaxf(u3, 0.f);
            }
            *(__half2*)&C[(size_t)r0       * ldc + n] = __floats2half2_rn(u0, u1);
            *(__half2*)&C[(size_t)(r0 + 8) * ldc + n] = __floats2half2_rn(u2, u3);
        }
    }
}

// ---------------------------------------------------------------------------
// GRU gates: 8 elements/thread, all fp16 I/O, fp32 math.
// ---------------------------------------------------------------------------
__device__ __forceinline__ float sig_(float x)  { return 1.f / (1.f + __expf(-x)); }
__device__ __forceinline__ float tanh_(float x) { float e = __expf(2.f * x); return 1.f - 2.f / (e + 1.f); }

__device__ __forceinline__ void load8h(float* f, const __half* p) {
    const uint4 v = *(const uint4*)p;
    const __half2* h2 = (const __half2*)&v;
    #pragma unroll
    for (int m = 0; m < 4; m++) {
        const float2 t = __half22float2(h2[m]);
        f[2 * m] = t.x; f[2 * m + 1] = t.y;
    }
}

__global__ void gru_gates(const __half* __restrict__ gi, int ldi,
                          const __half* __restrict__ gh, int ldh,
                          const __half* __restrict__ hprev,
                          __half* __restrict__ hnew)
{
    const int idx = blockIdx.x * blockDim.x + threadIdx.x;
    if (idx >= BATCH * HDIM / 8) return;
    const int b = idx >> 5;
    const int q = (idx & 31) * 8;

    const __half* gib = gi + (size_t)b * ldi + q;
    const __half* ghb = gh + (size_t)b * ldh + q;

    float ir[8], iz[8], in_[8], hr[8], hz[8], hn[8], hpl[8];
    load8h(ir,  gib);
    load8h(iz,  gib + 256);
    load8h(in_, gib + 512);
    load8h(hr,  ghb);
    load8h(hz,  ghb + 256);
    load8h(hn,  ghb + 512);
    load8h(hpl, hprev + (size_t)b * HDIM + q);

    __half2 o[4];
    #pragma unroll
    for (int m = 0; m < 4; m++) {
        float ho[2];
        #pragma unroll
        for (int u = 0; u < 2; u++) {
            const int k = 2 * m + u;
            const float r = sig_(ir[k] + hr[k]);
            const float z = sig_(iz[k] + hz[k]);
            const float n = tanh_(in_[k] + r * hn[k]);
            ho[u] = (1.f - z) * n + z * hpl[k];
        }
        o[m] = __floats2half2_rn(ho[0], ho[1]);
    }
    *(uint4*)(hnew + (size_t)b * HDIM + q) = *(uint4*)o;
}

// ---------------------------------------------------------------------------
// prep kernels
// ---------------------------------------------------------------------------
__global__ void conv16(const float* __restrict__ src, __half* __restrict__ dst,
                       int N, int K, int Kpad)
{
    const int idx = blockIdx.x * blockDim.x + threadIdx.x;
    if (idx >= N * Kpad) return;
    const int row = idx / Kpad;
    const int k   = idx % Kpad;
    const float v = (k < K) ? src[(size_t)row * K + k] : 0.f;
    dst[idx] = __float2half_rn(v);
}

__global__ void prep_bcat(const float* __restrict__ bih0, const float* __restrict__ bhh1)
{
    const int idx = blockIdx.x * blockDim.x + threadIdx.x;
    if (idx < 768)       g_bcat[idx] = bih0[idx];
    else if (idx < 1536) g_bcat[idx] = bhh1[idx - 768];
}

__global__ void zero_h(__half* __restrict__ p, int n)   // n in half2 units
{
    const int idx = blockIdx.x * blockDim.x + threadIdx.x;
    if (idx < n) ((__half2*)p)[idx] = __floats2half2_rn(0.f, 0.f);
}

// ---------------------------------------------------------------------------
// Fused FC + ReLU + softmax (V=42), one warp per (b, t). hist fp16.
// ---------------------------------------------------------------------------
__global__ void __launch_bounds__(256)
fc_softmax_kernel(const __half* __restrict__ hist,
                  const float* __restrict__ wfc,
                  const float* __restrict__ bfc,
                  float* __restrict__ out)
{
    const int gwarp = (blockIdx.x * blockDim.x + threadIdx.x) >> 5;
    const int lane  = threadIdx.x & 31;
    const int wl    = threadIdx.x >> 5;
    if (gwarp >= BATCH * TSTEPS) return;
    const int b = gwarp / TSTEPS;
    const int t = gwarp % TSTEPS;

    __shared__ float hs[8][HDIM];
    const __half* h = hist + ((size_t)(t + 1) * BATCH + b) * HDIM;
    #pragma unroll
    for (int k = 0; k < HDIM / 64; k++) {
        const __half2 hv = *(const __half2*)&h[2 * (lane + k * 32)];
        const float2 f = __half22float2(hv);
        hs[wl][2 * (lane + k * 32)]     = f.x;
        hs[wl][2 * (lane + k * 32) + 1] = f.y;
    }
    __syncwarp();

    const float* hrow = hs[wl];
    const bool has2 = (lane < VDIM - 32);

    float v0 = bfc[lane];
    {
        const float4* w4 = (const float4*)&wfc[(size_t)lane * HDIM];
        float a = 0.f;
        #pragma unroll 8
        for (int k = 0; k < HDIM / 4; k++) {
            const float4 wv = w4[k];
            const float4 hv = *(const float4*)&hrow[k * 4];
            a += wv.x * hv.x + wv.y * hv.y + wv.z * hv.z + wv.w * hv.w;
        }
        v0 += a;
    }
    float v1 = -1e30f;
    if (has2) {
        v1 = bfc[lane + 32];
        const float4* w4 = (const float4*)&wfc[(size_t)(lane + 32) * HDIM];
        float a = 0.f;
        #pragma unroll 8
        for (int k = 0; k < HDIM / 4; k++) {
            const float4 wv = w4[k];
            const float4 hv = *(const float4*)&hrow[k * 4];
            a += wv.x * hv.x + wv.y * hv.y + wv.z * hv.z + wv.w * hv.w;
        }
        v1 += a;
    }

    v0 = fmaxf(v0, 0.f);
    const float lv1 = has2 ? fmaxf(v1, 0.f) : -1e30f;

    float m = fmaxf(v0, lv1);
    #pragma unroll
    for (int off = 16; off; off >>= 1) m = fmaxf(m, __shfl_xor_sync(0xffffffffu, m, off));

    const float e0 = expf(v0 - m);
    const float e1 = has2 ? expf(lv1 - m) : 0.f;
    float s = e0 + e1;
    #pragma unroll
    for (int off = 16; off; off >>= 1) s += __shfl_xor_sync(0xffffffffu, s, off);

    const float inv = 1.f / s;
    float* o = out + (size_t)gwarp * VDIM;
    o[lane] = e0 * inv;
    if (has2) o[lane + 32] = e1 * inv;
}

// ---------------------------------------------------------------------------
// Launch
// ---------------------------------------------------------------------------
extern "C" void kernel_launch(void* const* d_in, const int* in_sizes, int n_in,
                              void* d_out, int out_size)
{
    const float* x    = (const float*)d_in[0];
    const float* w1   = (const float*)d_in[1];
    const float* b1   = (const float*)d_in[2];
    const float* w2   = (const float*)d_in[3];
    const float* b2   = (const float*)d_in[4];
    const float* w3   = (const float*)d_in[5];
    const float* b3   = (const float*)d_in[6];
    const float* w4   = (const float*)d_in[7];
    const float* b4   = (const float*)d_in[8];
    const float* wih0 = (const float*)d_in[9];
    const float* whh0 = (const float*)d_in[10];
    const float* bih0 = (const float*)d_in[11];
    const float* bhh0 = (const float*)d_in[12];
    const float* wih1 = (const float*)d_in[13];
    const float* whh1 = (const float*)d_in[14];
    const float* bih1 = (const float*)d_in[15];
    const float* bhh1 = (const float*)d_in[16];
    const float* wfc  = (const float*)d_in[17];
    const float* bfc  = (const float*)d_in[18];
    float* out = (float*)d_out;

    __half *x16, *w1h, *w2h, *w3h, *w4h, *wcath, *whh0h, *wih1h;
    __half *act0h, *act1h, *e, *h0, *hist, *giA, *gh0, *gi1;
    float *bcat;
    cudaGetSymbolAddress((void**)&x16,   g_x16);
    cudaGetSymbolAddress((void**)&w1h,   g_w1h);
    cudaGetSymbolAddress((void**)&w2h,   g_w2h);
    cudaGetSymbolAddress((void**)&w3h,   g_w3h);
    cudaGetSymbolAddress((void**)&w4h,   g_w4h);
    cudaGetSymbolAddress((void**)&wcath, g_wcath);
    cudaGetSymbolAddress((void**)&whh0h, g_whh0h);
    cudaGetSymbolAddress((void**)&wih1h, g_wih1h);
    cudaGetSymbolAddress((void**)&act0h, g_act0h);
    cudaGetSymbolAddress((void**)&act1h, g_act1h);
    cudaGetSymbolAddress((void**)&e,     g_e);
    cudaGetSymbolAddress((void**)&h0,    g_h0);
    cudaGetSymbolAddress((void**)&hist,  g_hist);
    cudaGetSymbolAddress((void**)&giA,   g_giA);
    cudaGetSymbolAddress((void**)&gh0,   g_gh0);
    cudaGetSymbolAddress((void**)&gi1,   g_gi1);
    cudaGetSymbolAddress((void**)&bcat,  g_bcat);

    static bool attr_set = false;
    if (!attr_set) {
        cudaFuncSetAttribute(hgemm<true >, cudaFuncAttributeMaxDynamicSharedMemorySize, SMEM_TOT);
        cudaFuncSetAttribute(hgemm<false>, cudaFuncAttributeMaxDynamicSharedMemorySize, SMEM_TOT);
        attr_set = true;
    }

    const int BH = BATCH * HDIM;

    // ---- prep: fp32 -> fp16 conversions ----
    #define CONV(src, dst, N, K, Kp) \
        conv16<<<(int)(((size_t)(N) * (Kp) + 255) / 256), 256>>>(src, dst, N, K, Kp)
    CONV(x,    x16,   BATCH, FPDIM, FPPAD);
    CONV(w1,   w1h,   2048,  FPDIM, FPPAD);
    CONV(w2,   w2h,   1024,  2048,  2048);
    CONV(w3,   w3h,   512,   1024,  1024);
    CONV(w4,   w4h,   256,   512,   512);
    CONV(wih0, wcath, 768,   256,   256);
    CONV(whh1, wcath + (size_t)768 * 256, 768, 256, 256);
    CONV(whh0, whh0h, 768,   256,   256);
    CONV(wih1, wih1h, 768,   256,   256);
    prep_bcat<<<6, 256>>>(bih0, bhh1);
    zero_h<<<(BH / 2 + 255) / 256, 256>>>(h0, BH / 2);
    zero_h<<<(BH / 2 + 255) / 256, 256>>>(hist, BH / 2);

    // ---- encoder MLP (fp16 activations) ----
    {
        GemmP p;
        p = { x16,   w1h, b1, act0h, 2048 };
        hgemm<true><<<dim3(16, 64), 128, SMEM_TOT>>>(p, p, 99, FPPAD, FPPAD);
        p = { act0h, w2h, b2, act1h, 1024 };
        hgemm<true><<<dim3(8,  64), 128, SMEM_TOT>>>(p, p, 99, 2048, 2048);
        p = { act1h, w3h, b3, act0h, 512 };
        hgemm<true><<<dim3(4,  64), 128, SMEM_TOT>>>(p, p, 99, 1024, 1024);
        p = { act0h, w4h, b4, e, 256 };
        hgemm<true><<<dim3(2,  64), 128, SMEM_TOT>>>(p, p, 99, 512, 512);
    }

    // ---- GRU over T steps ----
    const int gatesBlocks = (BH / 8 + 255) / 256;

    for (int t = 0; t < TSTEPS; t++) {
        const __half* h1prev = hist + (size_t)t * BH;
        __half*       h1new  = hist + (size_t)(t + 1) * BH;

        if (t == 0) {
            GemmP pa = { e,       wcath,                     bcat,       giA,       1536 };
            GemmP pb = { h1prev,  wcath + (size_t)768 * 256, bcat + 768, giA + 768, 1536 };
            hgemm<false><<<dim3(12, 64), 128, SMEM_TOT>>>(pa, pb, 6, HDIM, 256);
            GemmP pc = { h0, whh0h, bhh0, gh0, 768 };
            hgemm<false><<<dim3(6, 64), 128, SMEM_TOT>>>(pc, pc, 99, HDIM, 256);
        } else {
            GemmP pa = { h1prev, wcath, bcat, giA, 1536 };
            GemmP pb = { h0,     whh0h, bhh0, gh0, 768 };
            hgemm<false><<<dim3(18, 64), 128, SMEM_TOT>>>(pa, pb, 12, HDIM, 256);
        }
        gru_gates<<<gatesBlocks, 256>>>(giA, 1536, gh0, 768, h0, h0);
        {
            GemmP p = { h0, wih1h, bih1, gi1, 768 };
            hgemm<false><<<dim3(6, 64), 128, SMEM_TOT>>>(p, p, 99, HDIM, 256);
        }
        gru_gates<<<gatesBlocks, 256>>>(gi1, 768, giA + 768, 1536, h1prev, h1new);
    }

    // ---- fused FC + ReLU + softmax ----
    const long long totalWarps = (long long)BATCH * TSTEPS;
    const int fcBlocks = (int)((totalWarps * 32 + 255) / 256);
    fc_softmax_kernel<<<fcBlocks, 256>>>(hist, wfc, bfc, out);
}

// round 8
// speedup vs baseline: 3.5801x; 1.0377x over previous
#include <cuda_runtime.h>
#include <cuda_fp16.h>
#include <math.h>
#include <stdint.h>

#define BATCH   8192
#define FPDIM   4860
#define FPPAD   4864
#define EDIM    256
#define HDIM    256
#define VDIM    42
#define TSTEPS  128

// ---------------------------------------------------------------------------
// Static device scratch
// ---------------------------------------------------------------------------
__device__ __half g_x16  [(size_t)BATCH * FPPAD];
__device__ __half g_w1h  [(size_t)2048 * FPPAD];
__device__ __half g_w2h  [(size_t)1024 * 2048];
__device__ __half g_w3h  [(size_t)512 * 1024];
__device__ __half g_w4h  [(size_t)256 * 512];

__device__ __half g_act0h[(size_t)BATCH * 2048];
__device__ __half g_act1h[(size_t)BATCH * 1024];
__device__ __half g_e    [(size_t)BATCH * EDIM];
__device__ __half g_h0buf[2][(size_t)BATCH * HDIM];
__device__ __half g_hist [(size_t)(TSTEPS + 1) * BATCH * HDIM];

// GRU layer weights, virtual-N layout: row = hb*256 + gate*64 + rr, K=512
// gate 0 (r): [wih_r | whh_r]   gate 1 (z): [wih_z | whh_z]
// gate 2 (in): [wih_n | 0]      gate 3 (hn): [0 | whh_n]
__device__ __half g_wv[2][(size_t)1024 * 512];
__device__ float  g_bv[2][1024];   // [br | bz | bih_n | bhh_n]

// ---------------------------------------------------------------------------
// helpers
// ---------------------------------------------------------------------------
__device__ __forceinline__ uint32_t smem_u32(const void* p) {
    return (uint32_t)__cvta_generic_to_shared(p);
}
__device__ __forceinline__ void cp_async16(uint32_t dst, const void* src) {
    asm volatile("cp.async.cg.shared.global [%0], [%1], 16;\n"
                 :: "r"(dst), "l"(src));
}
#define CP_COMMIT()  asm volatile("cp.async.commit_group;\n")
#define CP_WAIT2()   asm volatile("cp.async.wait_group 2;\n")

#define SWZ(x) ((x) ^ (((x) >> 3) & 0x70))

__device__ __forceinline__ void ldm4(uint32_t addr, uint32_t& r0, uint32_t& r1,
                                     uint32_t& r2, uint32_t& r3) {
    asm volatile("ldmatrix.sync.aligned.m8n8.x4.shared.b16 {%0,%1,%2,%3}, [%4];"
                 : "=r"(r0), "=r"(r1), "=r"(r2), "=r"(r3) : "r"(addr));
}
__device__ __forceinline__ void mma16816(float c[4], const uint32_t a[4],
                                         uint32_t b0, uint32_t b1) {
    asm volatile("mma.sync.aligned.m16n8k16.row.col.f32.f16.f16.f32 "
                 "{%0,%1,%2,%3}, {%4,%5,%6,%7}, {%8,%9}, {%0,%1,%2,%3};"
                 : "+f"(c[0]), "+f"(c[1]), "+f"(c[2]), "+f"(c[3])
                 : "r"(a[0]), "r"(a[1]), "r"(a[2]), "r"(a[3]),
                   "r"(b0), "r"(b1));
}

__device__ __forceinline__ float sig_(float x)  { return 1.f / (1.f + __expf(-x)); }
__device__ __forceinline__ float tanh_(float x) { float e = __expf(2.f * x); return 1.f - 2.f / (e + 1.f); }

// ---------------------------------------------------------------------------
// Fused GRU layer kernel.
//   gates = A_v @ Wv^T where A-lo (kt 0-3) = xin, A-hi (kt 4-7) = hin.
//   CTA: M=128 rows x 64 hidden cols (4 gate strips of 64 v-cols).
//   grid (4, 64). 256 threads = 8 warps: 2 (M) x 4 (h-quarter of 16 cols).
//   Epilogue: per-thread gate math -> hout = (1-z)*n + z*hold.
// ---------------------------------------------------------------------------
#define L_NSTG    3
#define L_ATILE   16384                    // 128 x 128B
#define L_BTILE   32768                    // 256 x 128B
#define L_STAGE   (L_ATILE + L_BTILE)      // 48 KB
#define L_SMEM    (L_NSTG * L_STAGE)       // 144 KB

__global__ void __launch_bounds__(256, 1)
gru_layer(const __half* __restrict__ xin,   // input sequence element (lda 256)
          const __half* __restrict__ hin,   // hidden state h_{t-1}   (lda 256)
          const __half* __restrict__ wv,    // 1024 x 512 virtual weights
          const float*  __restrict__ bv,    // 1024 biases
          __half* __restrict__ hout)        // new hidden (lda 256)
{
    extern __shared__ __half sh[];
    const uint32_t sbase = smem_u32(sh);

    const int tid  = threadIdx.x;
    const int hb   = blockIdx.x;            // hidden block (64 cols)
    const int bm   = blockIdx.y * 128;
    const int w    = tid >> 5;
    const int lane = tid & 31;
    const int wm   = (w & 1) * 64;
    const int hq   = (w >> 1) * 16;         // h-quarter within 64

    float acc[4][4][2][4];                   // [gate][mfrag][n8grp][4]
    #pragma unroll
    for (int g = 0; g < 4; g++)
        #pragma unroll
        for (int i = 0; i < 4; i++)
            #pragma unroll
            for (int n = 0; n < 2; n++)
                #pragma unroll
                for (int q = 0; q < 4; q++) acc[g][i][n][q] = 0.f;

    auto issue = [&](int kt) {
        const uint32_t st = sbase + (kt % L_NSTG) * L_STAGE;
        const __half* aptr = (kt < 4) ? xin : hin;
        const int akoff = (kt & 3) * 64;
        #pragma unroll
        for (int i = 0; i < 4; i++) {
            const int c = i * 256 + tid;         // 0..1023
            const int row = c >> 3, cc = c & 7;
            cp_async16(st + SWZ((row << 7) + (cc << 4)),
                       aptr + (size_t)(bm + row) * 256 + akoff + cc * 8);
        }
        const uint32_t bB = st + L_ATILE;
        #pragma unroll
        for (int i = 0; i < 6; i++) {
            const int c = i * 256 + tid;         // 0..1535
            const int rp = c >> 3, cc = c & 7;
            const int g = (rp < 128) ? (rp >> 6) : ((kt < 4) ? 2 : 3);
            const int brow = g * 64 + (rp & 63);
            cp_async16(bB + SWZ((brow << 7) + (cc << 4)),
                       wv + ((size_t)(hb << 8) + brow) * 512 + kt * 64 + cc * 8);
        }
        CP_COMMIT();
    };

    issue(0); issue(1); issue(2);

    const int arow = wm + (lane & 15);
    const int abyt = (lane >> 4) << 4;
    const int brL  = ((lane >> 4) << 3) + (lane & 7);
    const int bbyt = ((lane >> 3) & 1) << 4;

    #pragma unroll
    for (int half = 0; half < 2; half++) {
        const int GX = (half == 0) ? 2 : 3;       // active 3rd gate
        #pragma unroll
        for (int kt4 = 0; kt4 < 4; kt4++) {
            const int kt = half * 4 + kt4;
            CP_WAIT2();
            __syncthreads();
            const uint32_t st = sbase + (kt % L_NSTG) * L_STAGE;
            const uint32_t bB = st + L_ATILE;

            #pragma unroll
            for (int s = 0; s < 4; s++) {
                uint32_t a[4][4];
                #pragma unroll
                for (int i = 0; i < 4; i++)
                    ldm4(st + SWZ(((arow + i * 16) << 7) + s * 32 + abyt),
                         a[i][0], a[i][1], a[i][2], a[i][3]);
                const int gs[3] = { 0, 1, GX };
                #pragma unroll
                for (int gi = 0; gi < 3; gi++) {
                    const int g = gs[gi];
                    uint32_t b0, b1, b2, b3;
                    ldm4(bB + SWZ(((g * 64 + hq + brL) << 7) + s * 32 + bbyt),
                         b0, b1, b2, b3);
                    #pragma unroll
                    for (int i = 0; i < 4; i++) {
                        mma16816(acc[g][i][0], a[i], b0, b1);
                        mma16816(acc[g][i][1], a[i], b2, b3);
                    }
                }
            }
            __syncthreads();
            if (kt + L_NSTG < 8) issue(kt + L_NSTG);
            else                 CP_COMMIT();
        }
    }

    // ---- epilogue: per-thread gate math ----
    const int col0 = hb * 64 + hq + (lane & 3) * 2;
    float2 br[2], bz[2], bi[2], bh[2];
    #pragma unroll
    for (int n2 = 0; n2 < 2; n2++) {
        const int c = col0 + n2 * 8;
        br[n2] = *(const float2*)(bv +       c);
        bz[n2] = *(const float2*)(bv + 256 + c);
        bi[n2] = *(const float2*)(bv + 512 + c);
        bh[n2] = *(const float2*)(bv + 768 + c);
    }

    #pragma unroll
    for (int mf = 0; mf < 4; mf++) {
        const int m0 = bm + wm + mf * 16 + (lane >> 2);
        #pragma unroll
        for (int n2 = 0; n2 < 2; n2++) {
            const int col = col0 + n2 * 8;
            #pragma unroll
            for (int rh = 0; rh < 2; rh++) {
                const int m = m0 + rh * 8;
                const float r0 = sig_(acc[0][mf][n2][rh * 2 + 0] + br[n2].x);
                const float r1 = sig_(acc[0][mf][n2][rh * 2 + 1] + br[n2].y);
                const float z0 = sig_(acc[1][mf][n2][rh * 2 + 0] + bz[n2].x);
                const float z1 = sig_(acc[1][mf][n2][rh * 2 + 1] + bz[n2].y);
                const float n0 = tanh_(acc[2][mf][n2][rh * 2 + 0] + bi[n2].x
                                       + r0 * (acc[3][mf][n2][rh * 2 + 0] + bh[n2].x));
                const float n1 = tanh_(acc[2][mf][n2][rh * 2 + 1] + bi[n2].y
                                       + r1 * (acc[3][mf][n2][rh * 2 + 1] + bh[n2].y));
                const __half2 hv = *(const __half2*)(hin + (size_t)m * 256 + col);
                const float2 ho = __half22float2(hv);
                const float h0n = (1.f - z0) * n0 + z0 * ho.x;
                const float h1n = (1.f - z1) * n1 + z1 * ho.y;
                *(__half2*)(hout + (size_t)m * 256 + col) = __floats2half2_rn(h0n, h1n);
            }
        }
    }
}

// ---------------------------------------------------------------------------
// FP16 tensor GEMM for the encoder (unchanged from R7; verified correct).
// ---------------------------------------------------------------------------
#define NSTG     3
#define TILE_B   16384
#define STAGE_B  (2 * TILE_B)
#define SMEM_TOT (NSTG * STAGE_B)

struct GemmP { const __half* A; const __half* W; const float* bias; __half* C; int ldc; };

template<bool RELU>
__global__ void __launch_bounds__(128, 2)
hgemm(GemmP p0, GemmP p1, int split, int lda, int K)
{
    extern __shared__ __half sh[];
    const uint32_t sbase = smem_u32(sh);

    const int tid  = threadIdx.x;
    int bxx = blockIdx.x;
    GemmP P = p0;
    if (bxx >= split) { P = p1; bxx -= split; }
    const int bm = blockIdx.y * 128;
    const int bn = bxx * 128;

    const int w    = tid >> 5;
    const int lane = tid & 31;
    const int wm   = (w & 1) * 64;
    const int wn   = (w >> 1) * 64;
    const int g    = lane >> 2;
    const int tg   = lane & 3;

    float acc[4][8][4];
    #pragma unroll
    for (int i = 0; i < 4; i++)
        #pragma unroll
        for (int j = 0; j < 8; j++)
            #pragma unroll
            for (int q = 0; q < 4; q++) acc[i][j][q] = 0.f;

    const int KT = K >> 6;
    const __half* A = P.A;
    const __half* W = P.W;

    auto issue = [&](int kt) {
        const uint32_t st = sbase + (kt % NSTG) * STAGE_B;
        const int koff = kt * 64;
        #pragma unroll
        for (int i = 0; i < 8; i++) {
            const int c = i * 128 + tid;
            const int row = c >> 3, col = c & 7;
            cp_async16(st + SWZ((row << 7) + (col << 4)),
                       A + (size_t)(bm + row) * lda + koff + col * 8);
        }
        #pragma unroll
        for (int i = 0; i < 8; i++) {
            const int c = i * 128 + tid;
            const int row = c >> 3, col = c & 7;
            cp_async16(st + TILE_B + SWZ((row << 7) + (col << 4)),
                       W + (size_t)(bn + row) * K + koff + col * 8);
        }
        CP_COMMIT();
    };

    issue(0); issue(1); issue(2);

    const int arow = wm + (lane & 15);
    const int abyt = (lane >> 4) << 4;
    const int brow = wn + ((lane >> 4) << 3) + (lane & 7);
    const int bbyt = ((lane >> 3) & 1) << 4;

    for (int kt = 0; kt < KT; kt++) {
        CP_WAIT2();
        __syncthreads();

        const uint32_t st = sbase + (kt % NSTG) * STAGE_B;

        #pragma unroll
        for (int s = 0; s < 4; s++) {
            uint32_t a[4][4], b[4][4];
            #pragma unroll
            for (int i = 0; i < 4; i++)
                ldm4(st + SWZ(((arow + i * 16) << 7) + s * 32 + abyt),
                     a[i][0], a[i][1], a[i][2], a[i][3]);
            #pragma unroll
            for (int j2 = 0; j2 < 4; j2++)
                ldm4(st + TILE_B + SWZ(((brow + j2 * 16) << 7) + s * 32 + bbyt),
                     b[j2][0], b[j2][1], b[j2][2], b[j2][3]);
            #pragma unroll
            for (int i = 0; i < 4; i++)
                #pragma unroll
                for (int j = 0; j < 8; j++)
                    mma16816(acc[i][j], a[i],
                             b[j >> 1][(j & 1) * 2], b[j >> 1][(j & 1) * 2 + 1]);
        }
        __syncthreads();
        if (kt + NSTG < KT) issue(kt + NSTG);
        else                CP_COMMIT();
    }

    const float* bias = P.bias;
    __half* C = P.C;
    const int ldc = P.ldc;

    float bx[8], by[8];
    #pragma unroll
    for (int j = 0; j < 8; j++) {
        const int n = bn + wn + j * 8 + 2 * tg;
        bx[j] = bias[n]; by[j] = bias[n + 1];
    }
    #pragma unroll
    for (int i = 0; i < 4; i++) {
        const int r0 = bm + wm + i * 16 + g;
        #pragma unroll
        for (int j = 0; j < 8; j++) {
            const int n = bn + wn + j * 8 + 2 * tg;
            float u0 = acc[i][j][0] + bx[j], u1 = acc[i][j][1] + by[j];
            float u2 = acc[i][j][2] + bx[j], u3 = acc[i][j][3] + by[j];
            if (RELU) {
                u0 = fmaxf(u0, 0.f); u1 = fmaxf(u1, 0.f);
                u2 = fmaxf(u2, 0.f); u3 = fmaxf(u3, 0.f);
            }
            *(__half2*)&C[(size_t)r0       * ldc + n] = __floats2half2_rn(u0, u1);
            *(__half2*)&C[(size_t)(r0 + 8) * ldc + n] = __floats2half2_rn(u2, u3);
        }
    }
}

// ---------------------------------------------------------------------------
// prep kernels
// ---------------------------------------------------------------------------
__global__ void conv16(const float* __restrict__ src, __half* __restrict__ dst,
                       int N, int K, int Kpad)
{
    const int idx = blockIdx.x * blockDim.x + threadIdx.x;
    if (idx >= N * Kpad) return;
    const int row = idx / Kpad;
    const int k   = idx % Kpad;
    const float v = (k < K) ? src[(size_t)row * K + k] : 0.f;
    dst[idx] = __float2half_rn(v);
}

// Build virtual-N weight matrix for a GRU layer.
__global__ void prep_wv(const float* __restrict__ wih, const float* __restrict__ whh,
                        __half* __restrict__ wv)
{
    const int idx = blockIdx.x * blockDim.x + threadIdx.x;
    if (idx >= 1024 * 512) return;
    const int row = idx >> 9;          // 0..1023
    const int k   = idx & 511;
    const int hb  = row >> 8;
    const int rem = row & 255;
    const int g   = rem >> 6;
    const int rr  = rem & 63;
    const int hc  = hb * 64 + rr;      // hidden unit index 0..255

    float v = 0.f;
    if (g == 0)      v = (k < 256) ? wih[(size_t)hc * 256 + k]         : whh[(size_t)hc * 256 + k - 256];
    else if (g == 1) v = (k < 256) ? wih[(size_t)(256 + hc) * 256 + k] : whh[(size_t)(256 + hc) * 256 + k - 256];
    else if (g == 2) v = (k < 256) ? wih[(size_t)(512 + hc) * 256 + k] : 0.f;
    else             v = (k < 256) ? 0.f : whh[(size_t)(512 + hc) * 256 + k - 256];
    wv[idx] = __float2half_rn(v);
}

__global__ void prep_bv(const float* __restrict__ bih, const float* __restrict__ bhh,
                        float* __restrict__ bv)
{
    const int idx = blockIdx.x * blockDim.x + threadIdx.x;
    if (idx >= 1024) return;
    const int g = idx >> 8, c = idx & 255;
    float v;
    if (g == 0)      v = bih[c]       + bhh[c];
    else if (g == 1) v = bih[256 + c] + bhh[256 + c];
    else if (g == 2) v = bih[512 + c];
    else             v = bhh[512 + c];
    bv[idx] = v;
}

__global__ void zero_h(__half* __restrict__ p, int n)   // n in half2 units
{
    const int idx = blockIdx.x * blockDim.x + threadIdx.x;
    if (idx < n) ((__half2*)p)[idx] = __floats2half2_rn(0.f, 0.f);
}

// ---------------------------------------------------------------------------
// Fused FC + ReLU + softmax (V=42), one warp per (b, t). hist fp16.
// ---------------------------------------------------------------------------
__global__ void __launch_bounds__(256)
fc_softmax_kernel(const __half* __restrict__ hist,
                  const float* __restrict__ wfc,
                  const float* __restrict__ bfc,
                  float* __restrict__ out)
{
    const int gwarp = (blockIdx.x * blockDim.x + threadIdx.x) >> 5;
    const int lane  = threadIdx.x & 31;
    const int wl    = threadIdx.x >> 5;
    if (gwarp >= BATCH * TSTEPS) return;
    const int b = gwarp / TSTEPS;
    const int t = gwarp % TSTEPS;

    __shared__ float hs[8][HDIM];
    const __half* h = hist + ((size_t)(t + 1) * BATCH + b) * HDIM;
    #pragma unroll
    for (int k = 0; k < HDIM / 64; k++) {
        const __half2 hv = *(const __half2*)&h[2 * (lane + k * 32)];
        const float2 f = __half22float2(hv);
        hs[wl][2 * (lane + k * 32)]     = f.x;
        hs[wl][2 * (lane + k * 32) + 1] = f.y;
    }
    __syncwarp();

    const float* hrow = hs[wl];
    const bool has2 = (lane < VDIM - 32);

    float v0 = bfc[lane];
    {
        const float4* w4 = (const float4*)&wfc[(size_t)lane * HDIM];
        float a = 0.f;
        #pragma unroll 8
        for (int k = 0; k < HDIM / 4; k++) {
            const float4 wv = w4[k];
            const float4 hv = *(const float4*)&hrow[k * 4];
            a += wv.x * hv.x + wv.y * hv.y + wv.z * hv.z + wv.w * hv.w;
        }
        v0 += a;
    }
    float v1 = -1e30f;
    if (has2) {
        v1 = bfc[lane + 32];
        const float4* w4 = (const float4*)&wfc[(size_t)(lane + 32) * HDIM];
        float a = 0.f;
        #pragma unroll 8
        for (int k = 0; k < HDIM / 4; k++) {
            const float4 wv = w4[k];
            const float4 hv = *(const float4*)&hrow[k * 4];
            a += wv.x * hv.x + wv.y * hv.y + wv.z * hv.z + wv.w * hv.w;
        }
        v1 += a;
    }

    v0 = fmaxf(v0, 0.f);
    const float lv1 = has2 ? fmaxf(v1, 0.f) : -1e30f;

    float m = fmaxf(v0, lv1);
    #pragma unroll
    for (int off = 16; off; off >>= 1) m = fmaxf(m, __shfl_xor_sync(0xffffffffu, m, off));

    const float e0 = expf(v0 - m);
    const float e1 = has2 ? expf(lv1 - m) : 0.f;
    float s = e0 + e1;
    #pragma unroll
    for (int off = 16; off; off >>= 1) s += __shfl_xor_sync(0xffffffffu, s, off);

    const float inv = 1.f / s;
    float* o = out + (size_t)gwarp * VDIM;
    o[lane] = e0 * inv;
    if (has2) o[lane + 32] = e1 * inv;
}

// ---------------------------------------------------------------------------
// Launch
// ---------------------------------------------------------------------------
extern "C" void kernel_launch(void* const* d_in, const int* in_sizes, int n_in,
                              void* d_out, int out_size)
{
    const float* x    = (const float*)d_in[0];
    const float* w1   = (const float*)d_in[1];
    const float* b1   = (const float*)d_in[2];
    const float* w2   = (const float*)d_in[3];
    const float* b2   = (const float*)d_in[4];
    const float* w3   = (const float*)d_in[5];
    const float* b3   = (const float*)d_in[6];
    const float* w4   = (const float*)d_in[7];
    const float* b4   = (const float*)d_in[8];
    const float* wih0 = (const float*)d_in[9];
    const float* whh0 = (const float*)d_in[10];
    const float* bih0 = (const float*)d_in[11];
    const float* bhh0 = (const float*)d_in[12];
    const float* wih1 = (const float*)d_in[13];
    const float* whh1 = (const float*)d_in[14];
    const float* bih1 = (const float*)d_in[15];
    const float* bhh1 = (const float*)d_in[16];
    const float* wfc  = (const float*)d_in[17];
    const float* bfc  = (const float*)d_in[18];
    float* out = (float*)d_out;

    __half *x16, *w1h, *w2h, *w3h, *w4h, *act0h, *act1h, *e, *hist;
    __half *h0a, *h0b, *wv0, *wv1;
    float *bv0, *bv1;
    cudaGetSymbolAddress((void**)&x16,   g_x16);
    cudaGetSymbolAddress((void**)&w1h,   g_w1h);
    cudaGetSymbolAddress((void**)&w2h,   g_w2h);
    cudaGetSymbolAddress((void**)&w3h,   g_w3h);
    cudaGetSymbolAddress((void**)&w4h,   g_w4h);
    cudaGetSymbolAddress((void**)&act0h, g_act0h);
    cudaGetSymbolAddress((void**)&act1h, g_act1h);
    cudaGetSymbolAddress((void**)&e,     g_e);
    cudaGetSymbolAddress((void**)&hist,  g_hist);
    { void* p; cudaGetSymbolAddress(&p, g_h0buf); h0a = (__half*)p; h0b = h0a + (size_t)BATCH * HDIM; }
    { void* p; cudaGetSymbolAddress(&p, g_wv);    wv0 = (__half*)p; wv1 = wv0 + (size_t)1024 * 512; }
    { void* p; cudaGetSymbolAddress(&p, g_bv);    bv0 = (float*)p;  bv1 = bv0 + 1024; }

    static bool attr_set = false;
    if (!attr_set) {
        cudaFuncSetAttribute(hgemm<true >, cudaFuncAttributeMaxDynamicSharedMemorySize, SMEM_TOT);
        cudaFuncSetAttribute(hgemm<false>, cudaFuncAttributeMaxDynamicSharedMemorySize, SMEM_TOT);
        cudaFuncSetAttribute(gru_layer,    cudaFuncAttributeMaxDynamicSharedMemorySize, L_SMEM);
        attr_set = true;
    }

    const int BH = BATCH * HDIM;

    // ---- prep ----
    #define CONV(src, dst, N, K, Kp) \
        conv16<<<(int)(((size_t)(N) * (Kp) + 255) / 256), 256>>>(src, dst, N, K, Kp)
    CONV(x,  x16, BATCH, FPDIM, FPPAD);
    CONV(w1, w1h, 2048,  FPDIM, FPPAD);
    CONV(w2, w2h, 1024,  2048,  2048);
    CONV(w3, w3h, 512,   1024,  1024);
    CONV(w4, w4h, 256,   512,   512);
    prep_wv<<<(1024 * 512 + 255) / 256, 256>>>(wih0, whh0, wv0);
    prep_wv<<<(1024 * 512 + 255) / 256, 256>>>(wih1, whh1, wv1);
    prep_bv<<<4, 256>>>(bih0, bhh0, bv0);
    prep_bv<<<4, 256>>>(bih1, bhh1, bv1);
    zero_h<<<(BH / 2 + 255) / 256, 256>>>(h0a, BH / 2);
    zero_h<<<(BH / 2 + 255) / 256, 256>>>(hist, BH / 2);

    // ---- encoder MLP ----
    {
        GemmP p;
        p = { x16,   w1h, b1, act0h, 2048 };
        hgemm<true><<<dim3(16, 64), 128, SMEM_TOT>>>(p, p, 99, FPPAD, FPPAD);
        p = { act0h, w2h, b2, act1h, 1024 };
        hgemm<true><<<dim3(8,  64), 128, SMEM_TOT>>>(p, p, 99, 2048, 2048);
        p = { act1h, w3h, b3, act0h, 512 };
        hgemm<true><<<dim3(4,  64), 128, SMEM_TOT>>>(p, p, 99, 1024, 1024);
        p = { act0h, w4h, b4, e, 256 };
        hgemm<true><<<dim3(2,  64), 128, SMEM_TOT>>>(p, p, 99, 512, 512);
    }

    // ---- GRU over T steps: 2 fused layer kernels per step ----
    for (int t = 0; t < TSTEPS; t++) {
        const __half* x0   = (t == 0) ? e : (hist + (size_t)t * BH);  // layer0 input
        __half* h0prev = (t & 1) ? h0b : h0a;
        __half* h0new  = (t & 1) ? h0a : h0b;
        const __half* h1prev = hist + (size_t)t * BH;
        __half*       h1new  = hist + (size_t)(t + 1) * BH;

        gru_layer<<<dim3(4, 64), 256, L_SMEM>>>(x0,    h0prev, wv0, bv0, h0new);
        gru_layer<<<dim3(4, 64), 256, L_SMEM>>>(h0new, h1prev, wv1, bv1, h1new);
    }

    // ---- fused FC + ReLU + softmax ----
    const long long totalWarps = (long long)BATCH * TSTEPS;
    const int fcBlocks = (int)((totalWarps * 32 + 255) / 256);
    fc_softmax_kernel<<<fcBlocks, 256>>>(hist, wfc, bfc, out);
}

// round 9
// speedup vs baseline: 3.8843x; 1.0850x over previous
#include <cuda_runtime.h>
#include <cuda_fp16.h>
#include <math.h>
#include <stdint.h>

#define BATCH   8192
#define FPDIM   4860
#define FPPAD   4864
#define EDIM    256
#define HDIM    256
#define VDIM    42
#define TSTEPS  128

// ---------------------------------------------------------------------------
// Static device scratch
// ---------------------------------------------------------------------------
__device__ __half g_x16  [(size_t)BATCH * FPPAD];
__device__ __half g_w1h  [(size_t)2048 * FPPAD];
__device__ __half g_w2h  [(size_t)1024 * 2048];
__device__ __half g_w3h  [(size_t)512 * 1024];
__device__ __half g_w4h  [(size_t)256 * 512];

__device__ __half g_act0h[(size_t)BATCH * 2048];
__device__ __half g_act1h[(size_t)BATCH * 1024];
__device__ __half g_e    [(size_t)BATCH * EDIM];
__device__ __half g_h0buf[2][(size_t)BATCH * HDIM];
__device__ __half g_hist [(size_t)(TSTEPS + 1) * BATCH * HDIM];

// GRU layer weights, virtual-N layout: row = hb*256 + gate*64 + rr, K=512
// gate 0 (r): [wih_r | whh_r]   gate 1 (z): [wih_z | whh_z]
// gate 2 (in): [wih_n | 0]      gate 3 (hn): [0 | whh_n]
__device__ __half g_wv[2][(size_t)1024 * 512];
__device__ float  g_bv[2][1024];   // [br | bz | bih_n | bhh_n]

// ---------------------------------------------------------------------------
// helpers
// ---------------------------------------------------------------------------
__device__ __forceinline__ uint32_t smem_u32(const void* p) {
    return (uint32_t)__cvta_generic_to_shared(p);
}
__device__ __forceinline__ void cp_async16(uint32_t dst, const void* src) {
    asm volatile("cp.async.cg.shared.global [%0], [%1], 16;\n"
                 :: "r"(dst), "l"(src));
}
#define CP_COMMIT()  asm volatile("cp.async.commit_group;\n")
#define CP_WAIT2()   asm volatile("cp.async.wait_group 2;\n")

#define SWZ(x) ((x) ^ (((x) >> 3) & 0x70))

__device__ __forceinline__ void ldm4(uint32_t addr, uint32_t& r0, uint32_t& r1,
                                     uint32_t& r2, uint32_t& r3) {
    asm volatile("ldmatrix.sync.aligned.m8n8.x4.shared.b16 {%0,%1,%2,%3}, [%4];"
                 : "=r"(r0), "=r"(r1), "=r"(r2), "=r"(r3) : "r"(addr));
}
__device__ __forceinline__ void mma16816(float c[4], const uint32_t a[4],
                                         uint32_t b0, uint32_t b1) {
    asm volatile("mma.sync.aligned.m16n8k16.row.col.f32.f16.f16.f32 "
                 "{%0,%1,%2,%3}, {%4,%5,%6,%7}, {%8,%9}, {%0,%1,%2,%3};"
                 : "+f"(c[0]), "+f"(c[1]), "+f"(c[2]), "+f"(c[3])
                 : "r"(a[0]), "r"(a[1]), "r"(a[2]), "r"(a[3]),
                   "r"(b0), "r"(b1));
}

__device__ __forceinline__ float sig_(float x)  { return 1.f / (1.f + __expf(-x)); }
__device__ __forceinline__ float tanh_(float x) { float e = __expf(2.f * x); return 1.f - 2.f / (e + 1.f); }

// ---------------------------------------------------------------------------
// Fused GRU layer kernel (v2: 512 threads, warp tile M32 x h16).
//   gates = A_v @ Wv^T where A-lo (kt 0-3) = xin, A-hi (kt 4-7) = hin.
//   CTA: M=128 rows x 64 hidden cols. B tile holds only the 3 active gate
//   strips (192 rows): [r | z | in-or-hn].
//   grid (4, 64), 16 warps: 4 (M) x 4 (h-quarter).
// ---------------------------------------------------------------------------
#define L_NSTG    3
#define L_ATILE   16384                    // 128 x 128B
#define L_BTILE   24576                    // 192 x 128B (active strips only)
#define L_STAGE   (L_ATILE + L_BTILE)      // 40 KB
#define L_SMEM    (L_NSTG * L_STAGE)       // 120 KB

__global__ void __launch_bounds__(512, 1)
gru_layer(const __half* __restrict__ xin,   // input sequence element (lda 256)
          const __half* __restrict__ hin,   // hidden state h_{t-1}   (lda 256)
          const __half* __restrict__ wv,    // 1024 x 512 virtual weights
          const float*  __restrict__ bv,    // 1024 biases
          __half* __restrict__ hout)        // new hidden (lda 256)
{
    extern __shared__ __half sh[];
    const uint32_t sbase = smem_u32(sh);

    const int tid  = threadIdx.x;
    const int hb   = blockIdx.x;             // hidden block (64 cols)
    const int bm   = blockIdx.y * 128;
    const int w    = tid >> 5;
    const int lane = tid & 31;
    const int mq   = (w & 3) * 32;            // M-quarter (32 rows)
    const int hq   = (w >> 2) * 16;            // h-quarter (16 cols)

    float acc[4][2][2][4];                     // [gate][mfrag][n8grp][4]
    #pragma unroll
    for (int g = 0; g < 4; g++)
        #pragma unroll
        for (int i = 0; i < 2; i++)
            #pragma unroll
            for (int n = 0; n < 2; n++)
                #pragma unroll
                for (int q = 0; q < 4; q++) acc[g][i][n][q] = 0.f;

    auto issue = [&](int kt) {
        const uint32_t st = sbase + (kt % L_NSTG) * L_STAGE;
        const __half* aptr = (kt < 4) ? xin : hin;
        const int akoff = (kt & 3) * 64;
        #pragma unroll
        for (int i = 0; i < 2; i++) {
            const int c = i * 512 + tid;       // 0..1023
            const int row = c >> 3, cc = c & 7;
            cp_async16(st + SWZ((row << 7) + (cc << 4)),
                       aptr + (size_t)(bm + row) * 256 + akoff + cc * 8);
        }
        const uint32_t bB = st + L_ATILE;
        #pragma unroll
        for (int i = 0; i < 3; i++) {
            const int c = i * 512 + tid;       // 0..1535
            const int rp = c >> 3, cc = c & 7; // rp 0..191
            const int g = (rp < 128) ? (rp >> 6) : ((kt < 4) ? 2 : 3);
            const int wrow = g * 64 + (rp & 63);
            cp_async16(bB + SWZ((rp << 7) + (cc << 4)),
                       wv + ((size_t)(hb << 8) + wrow) * 512 + kt * 64 + cc * 8);
        }
        CP_COMMIT();
    };

    issue(0); issue(1); issue(2);

    const int arow = mq + (lane & 15);
    const int abyt = (lane >> 4) << 4;
    const int brL  = ((lane >> 4) << 3) + (lane & 7);
    const int bbyt = ((lane >> 3) & 1) << 4;

    #pragma unroll
    for (int half = 0; half < 2; half++) {
        const int GX = (half == 0) ? 2 : 3;        // acc slot for 3rd strip
        #pragma unroll
        for (int kt4 = 0; kt4 < 4; kt4++) {
            const int kt = half * 4 + kt4;
            CP_WAIT2();
            __syncthreads();
            const uint32_t st = sbase + (kt % L_NSTG) * L_STAGE;
            const uint32_t bB = st + L_ATILE;

            #pragma unroll
            for (int s = 0; s < 4; s++) {
                uint32_t a[2][4];
                #pragma unroll
                for (int i = 0; i < 2; i++)
                    ldm4(st + SWZ(((arow + i * 16) << 7) + s * 32 + abyt),
                         a[i][0], a[i][1], a[i][2], a[i][3]);
                #pragma unroll
                for (int gi = 0; gi < 3; gi++) {
                    const int ga = (gi < 2) ? gi : GX;
                    uint32_t b0, b1, b2, b3;
                    ldm4(bB + SWZ(((gi * 64 + hq + brL) << 7) + s * 32 + bbyt),
                         b0, b1, b2, b3);
                    #pragma unroll
                    for (int i = 0; i < 2; i++) {
                        mma16816(acc[ga][i][0], a[i], b0, b1);
                        mma16816(acc[ga][i][1], a[i], b2, b3);
                    }
                }
            }
            __syncthreads();
            if (kt + L_NSTG < 8) issue(kt + L_NSTG);
            else                 CP_COMMIT();
        }
    }

    // ---- epilogue: per-thread gate math ----
    const int col0 = hb * 64 + hq + (lane & 3) * 2;
    float2 br[2], bz[2], bi[2], bh[2];
    #pragma unroll
    for (int n2 = 0; n2 < 2; n2++) {
        const int c = col0 + n2 * 8;
        br[n2] = *(const float2*)(bv +       c);
        bz[n2] = *(const float2*)(bv + 256 + c);
        bi[n2] = *(const float2*)(bv + 512 + c);
        bh[n2] = *(const float2*)(bv + 768 + c);
    }

    #pragma unroll
    for (int mf = 0; mf < 2; mf++) {
        const int m0 = bm + mq + mf * 16 + (lane >> 2);
        #pragma unroll
        for (int n2 = 0; n2 < 2; n2++) {
            const int col = col0 + n2 * 8;
            #pragma unroll
            for (int rh = 0; rh < 2; rh++) {
                const int m = m0 + rh * 8;
                const float r0 = sig_(acc[0][mf][n2][rh * 2 + 0] + br[n2].x);
                const float r1 = sig_(acc[0][mf][n2][rh * 2 + 1] + br[n2].y);
                const float z0 = sig_(acc[1][mf][n2][rh * 2 + 0] + bz[n2].x);
                const float z1 = sig_(acc[1][mf][n2][rh * 2 + 1] + bz[n2].y);
                const float n0 = tanh_(acc[2][mf][n2][rh * 2 + 0] + bi[n2].x
                                       + r0 * (acc[3][mf][n2][rh * 2 + 0] + bh[n2].x));
                const float n1 = tanh_(acc[2][mf][n2][rh * 2 + 1] + bi[n2].y
                                       + r1 * (acc[3][mf][n2][rh * 2 + 1] + bh[n2].y));
                const __half2 hv = *(const __half2*)(hin + (size_t)m * 256 + col);
                const float2 ho = __half22float2(hv);
                const float h0n = (1.f - z0) * n0 + z0 * ho.x;
                const float h1n = (1.f - z1) * n1 + z1 * ho.y;
                *(__half2*)(hout + (size_t)m * 256 + col) = __floats2half2_rn(h0n, h1n);
            }
        }
    }
}

// ---------------------------------------------------------------------------
// FP16 tensor GEMM for the encoder (unchanged; verified correct).
// ---------------------------------------------------------------------------
#define NSTG     3
#define TILE_B   16384
#define STAGE_B  (2 * TILE_B)
#define SMEM_TOT (NSTG * STAGE_B)

struct GemmP { const __half* A; const __half* W; const float* bias; __half* C; int ldc; };

template<bool RELU>
__global__ void __launch_bounds__(128, 2)
hgemm(GemmP p0, GemmP p1, int split, int lda, int K)
{
    extern __shared__ __half sh[];
    const uint32_t sbase = smem_u32(sh);

    const int tid  = threadIdx.x;
    int bxx = blockIdx.x;
    GemmP P = p0;
    if (bxx >= split) { P = p1; bxx -= split; }
    const int bm = blockIdx.y * 128;
    const int bn = bxx * 128;

    const int w    = tid >> 5;
    const int lane = tid & 31;
    const int wm   = (w & 1) * 64;
    const int wn   = (w >> 1) * 64;
    const int g    = lane >> 2;
    const int tg   = lane & 3;

    float acc[4][8][4];
    #pragma unroll
    for (int i = 0; i < 4; i++)
        #pragma unroll
        for (int j = 0; j < 8; j++)
            #pragma unroll
            for (int q = 0; q < 4; q++) acc[i][j][q] = 0.f;

    const int KT = K >> 6;
    const __half* A = P.A;
    const __half* W = P.W;

    auto issue = [&](int kt) {
        const uint32_t st = sbase + (kt % NSTG) * STAGE_B;
        const int koff = kt * 64;
        #pragma unroll
        for (int i = 0; i < 8; i++) {
            const int c = i * 128 + tid;
            const int row = c >> 3, col = c & 7;
            cp_async16(st + SWZ((row << 7) + (col << 4)),
                       A + (size_t)(bm + row) * lda + koff + col * 8);
        }
        #pragma unroll
        for (int i = 0; i < 8; i++) {
            const int c = i * 128 + tid;
            const int row = c >> 3, col = c & 7;
            cp_async16(st + TILE_B + SWZ((row << 7) + (col << 4)),
                       W + (size_t)(bn + row) * K + koff + col * 8);
        }
        CP_COMMIT();
    };

    issue(0); issue(1); issue(2);

    const int arow = wm + (lane & 15);
    const int abyt = (lane >> 4) << 4;
    const int brow = wn + ((lane >> 4) << 3) + (lane & 7);
    const int bbyt = ((lane >> 3) & 1) << 4;

    for (int kt = 0; kt < KT; kt++) {
        CP_WAIT2();
        __syncthreads();

        const uint32_t st = sbase + (kt % NSTG) * STAGE_B;

        #pragma unroll
        for (int s = 0; s < 4; s++) {
            uint32_t a[4][4], b[4][4];
            #pragma unroll
            for (int i = 0; i < 4; i++)
                ldm4(st + SWZ(((arow + i * 16) << 7) + s * 32 + abyt),
                     a[i][0], a[i][1], a[i][2], a[i][3]);
            #pragma unroll
            for (int j2 = 0; j2 < 4; j2++)
                ldm4(st + TILE_B + SWZ(((brow + j2 * 16) << 7) + s * 32 + bbyt),
                     b[j2][0], b[j2][1], b[j2][2], b[j2][3]);
            #pragma unroll
            for (int i = 0; i < 4; i++)
                #pragma unroll
                for (int j = 0; j < 8; j++)
                    mma16816(acc[i][j], a[i],
                             b[j >> 1][(j & 1) * 2], b[j >> 1][(j & 1) * 2 + 1]);
        }
        __syncthreads();
        if (kt + NSTG < KT) issue(kt + NSTG);
        else                CP_COMMIT();
    }

    const float* bias = P.bias;
    __half* C = P.C;
    const int ldc = P.ldc;

    float bx[8], by[8];
    #pragma unroll
    for (int j = 0; j < 8; j++) {
        const int n = bn + wn + j * 8 + 2 * tg;
        bx[j] = bias[n]; by[j] = bias[n + 1];
    }
    #pragma unroll
    for (int i = 0; i < 4; i++) {
        const int r0 = bm + wm + i * 16 + g;
        #pragma unroll
        for (int j = 0; j < 8; j++) {
            const int n = bn + wn + j * 8 + 2 * tg;
            float u0 = acc[i][j][0] + bx[j], u1 = acc[i][j][1] + by[j];
            float u2 = acc[i][j][2] + bx[j], u3 = acc[i][j][3] + by[j];
            if (RELU) {
                u0 = fmaxf(u0, 0.f); u1 = fmaxf(u1, 0.f);
                u2 = fmaxf(u2, 0.f); u3 = fmaxf(u3, 0.f);
            }
            *(__half2*)&C[(size_t)r0       * ldc + n] = __floats2half2_rn(u0, u1);
            *(__half2*)&C[(size_t)(r0 + 8) * ldc + n] = __floats2half2_rn(u2, u3);
        }
    }
}

// ---------------------------------------------------------------------------
// prep kernels
// ---------------------------------------------------------------------------
__global__ void conv16(const float* __restrict__ src, __half* __restrict__ dst,
                       int N, int K, int Kpad)
{
    const int idx = blockIdx.x * blockDim.x + threadIdx.x;
    if (idx >= N * Kpad) return;
    const int row = idx / Kpad;
    const int k   = idx % Kpad;
    const float v = (k < K) ? src[(size_t)row * K + k] : 0.f;
    dst[idx] = __float2half_rn(v);
}

__global__ void prep_wv(const float* __restrict__ wih, const float* __restrict__ whh,
                        __half* __restrict__ wv)
{
    const int idx = blockIdx.x * blockDim.x + threadIdx.x;
    if (idx >= 1024 * 512) return;
    const int row = idx >> 9;
    const int k   = idx & 511;
    const int hb  = row >> 8;
    const int rem = row & 255;
    const int g   = rem >> 6;
    const int rr  = rem & 63;
    const int hc  = hb * 64 + rr;

    float v = 0.f;
    if (g == 0)      v = (k < 256) ? wih[(size_t)hc * 256 + k]         : whh[(size_t)hc * 256 + k - 256];
    else if (g == 1) v = (k < 256) ? wih[(size_t)(256 + hc) * 256 + k] : whh[(size_t)(256 + hc) * 256 + k - 256];
    else if (g == 2) v = (k < 256) ? wih[(size_t)(512 + hc) * 256 + k] : 0.f;
    else             v = (k < 256) ? 0.f : whh[(size_t)(512 + hc) * 256 + k - 256];
    wv[idx] = __float2half_rn(v);
}

__global__ void prep_bv(const float* __restrict__ bih, const float* __restrict__ bhh,
                        float* __restrict__ bv)
{
    const int idx = blockIdx.x * blockDim.x + threadIdx.x;
    if (idx >= 1024) return;
    const int g = idx >> 8, c = idx & 255;
    float v;
    if (g == 0)      v = bih[c]       + bhh[c];
    else if (g == 1) v = bih[256 + c] + bhh[256 + c];
    else if (g == 2) v = bih[512 + c];
    else             v = bhh[512 + c];
    bv[idx] = v;
}

__global__ void zero_h(__half* __restrict__ p, int n)   // n in half2 units
{
    const int idx = blockIdx.x * blockDim.x + threadIdx.x;
    if (idx < n) ((__half2*)p)[idx] = __floats2half2_rn(0.f, 0.f);
}

// ---------------------------------------------------------------------------
// Fused FC + ReLU + softmax (V=42), one warp per (b, t). hist fp16.
// ---------------------------------------------------------------------------
__global__ void __launch_bounds__(256)
fc_softmax_kernel(const __half* __restrict__ hist,
                  const float* __restrict__ wfc,
                  const float* __restrict__ bfc,
                  float* __restrict__ out)
{
    const int gwarp = (blockIdx.x * blockDim.x + threadIdx.x) >> 5;
    const int lane  = threadIdx.x & 31;
    const int wl    = threadIdx.x >> 5;
    if (gwarp >= BATCH * TSTEPS) return;
    const int b = gwarp / TSTEPS;
    const int t = gwarp % TSTEPS;

    __shared__ float hs[8][HDIM];
    const __half* h = hist + ((size_t)(t + 1) * BATCH + b) * HDIM;
    #pragma unroll
    for (int k = 0; k < HDIM / 64; k++) {
        const __half2 hv = *(const __half2*)&h[2 * (lane + k * 32)];
        const float2 f = __half22float2(hv);
        hs[wl][2 * (lane + k * 32)]     = f.x;
        hs[wl][2 * (lane + k * 32) + 1] = f.y;
    }
    __syncwarp();

    const float* hrow = hs[wl];
    const bool has2 = (lane < VDIM - 32);

    float v0 = bfc[lane];
    {
        const float4* w4 = (const float4*)&wfc[(size_t)lane * HDIM];
        float a = 0.f;
        #pragma unroll 8
        for (int k = 0; k < HDIM / 4; k++) {
            const float4 wv = w4[k];
            const float4 hv = *(const float4*)&hrow[k * 4];
            a += wv.x * hv.x + wv.y * hv.y + wv.z * hv.z + wv.w * hv.w;
        }
        v0 += a;
    }
    float v1 = -1e30f;
    if (has2) {
        v1 = bfc[lane + 32];
        const float4* w4 = (const float4*)&wfc[(size_t)(lane + 32) * HDIM];
        float a = 0.f;
        #pragma unroll 8
        for (int k = 0; k < HDIM / 4; k++) {
            const float4 wv = w4[k];
            const float4 hv = *(const float4*)&hrow[k * 4];
            a += wv.x * hv.x + wv.y * hv.y + wv.z * hv.z + wv.w * hv.w;
        }
        v1 += a;
    }

    v0 = fmaxf(v0, 0.f);
    const float lv1 = has2 ? fmaxf(v1, 0.f) : -1e30f;

    float m = fmaxf(v0, lv1);
    #pragma unroll
    for (int off = 16; off; off >>= 1) m = fmaxf(m, __shfl_xor_sync(0xffffffffu, m, off));

    const float e0 = expf(v0 - m);
    const float e1 = has2 ? expf(lv1 - m) : 0.f;
    float s = e0 + e1;
    #pragma unroll
    for (int off = 16; off; off >>= 1) s += __shfl_xor_sync(0xffffffffu, s, off);

    const float inv = 1.f / s;
    float* o = out + (size_t)gwarp * VDIM;
    o[lane] = e0 * inv;
    if (has2) o[lane + 32] = e1 * inv;
}

// ---------------------------------------------------------------------------
// Launch
// ---------------------------------------------------------------------------
extern "C" void kernel_launch(void* const* d_in, const int* in_sizes, int n_in,
                              void* d_out, int out_size)
{
    const float* x    = (const float*)d_in[0];
    const float* w1   = (const float*)d_in[1];
    const float* b1   = (const float*)d_in[2];
    const float* w2   = (const float*)d_in[3];
    const float* b2   = (const float*)d_in[4];
    const float* w3   = (const float*)d_in[5];
    const float* b3   = (const float*)d_in[6];
    const float* w4   = (const float*)d_in[7];
    const float* b4   = (const float*)d_in[8];
    const float* wih0 = (const float*)d_in[9];
    const float* whh0 = (const float*)d_in[10];
    const float* bih0 = (const float*)d_in[11];
    const float* bhh0 = (const float*)d_in[12];
    const float* wih1 = (const float*)d_in[13];
    const float* whh1 = (const float*)d_in[14];
    const float* bih1 = (const float*)d_in[15];
    const float* bhh1 = (const float*)d_in[16];
    const float* wfc  = (const float*)d_in[17];
    const float* bfc  = (const float*)d_in[18];
    float* out = (float*)d_out;

    __half *x16, *w1h, *w2h, *w3h, *w4h, *act0h, *act1h, *e, *hist;
    __half *h0a, *h0b, *wv0, *wv1;
    float *bv0, *bv1;
    cudaGetSymbolAddress((void**)&x16,   g_x16);
    cudaGetSymbolAddress((void**)&w1h,   g_w1h);
    cudaGetSymbolAddress((void**)&w2h,   g_w2h);
    cudaGetSymbolAddress((void**)&w3h,   g_w3h);
    cudaGetSymbolAddress((void**)&w4h,   g_w4h);
    cudaGetSymbolAddress((void**)&act0h, g_act0h);
    cudaGetSymbolAddress((void**)&act1h, g_act1h);
    cudaGetSymbolAddress((void**)&e,     g_e);
    cudaGetSymbolAddress((void**)&hist,  g_hist);
    { void* p; cudaGetSymbolAddress(&p, g_h0buf); h0a = (__half*)p; h0b = h0a + (size_t)BATCH * HDIM; }
    { void* p; cudaGetSymbolAddress(&p, g_wv);    wv0 = (__half*)p; wv1 = wv0 + (size_t)1024 * 512; }
    { void* p; cudaGetSymbolAddress(&p, g_bv);    bv0 = (float*)p;  bv1 = bv0 + 1024; }

    static bool attr_set = false;
    if (!attr_set) {
        cudaFuncSetAttribute(hgemm<true >, cudaFuncAttributeMaxDynamicSharedMemorySize, SMEM_TOT);
        cudaFuncSetAttribute(hgemm<false>, cudaFuncAttributeMaxDynamicSharedMemorySize, SMEM_TOT);
        cudaFuncSetAttribute(gru_layer,    cudaFuncAttributeMaxDynamicSharedMemorySize, L_SMEM);
        attr_set = true;
    }

    const int BH = BATCH * HDIM;

    // ---- prep ----
    #define CONV(src, dst, N, K, Kp) \
        conv16<<<(int)(((size_t)(N) * (Kp) + 255) / 256), 256>>>(src, dst, N, K, Kp)
    CONV(x,  x16, BATCH, FPDIM, FPPAD);
    CONV(w1, w1h, 2048,  FPDIM, FPPAD);
    CONV(w2, w2h, 1024,  2048,  2048);
    CONV(w3, w3h, 512,   1024,  1024);
    CONV(w4, w4h, 256,   512,   512);
    prep_wv<<<(1024 * 512 + 255) / 256, 256>>>(wih0, whh0, wv0);
    prep_wv<<<(1024 * 512 + 255) / 256, 256>>>(wih1, whh1, wv1);
    prep_bv<<<4, 256>>>(bih0, bhh0, bv0);
    prep_bv<<<4, 256>>>(bih1, bhh1, bv1);
    zero_h<<<(BH / 2 + 255) / 256, 256>>>(h0a, BH / 2);
    zero_h<<<(BH / 2 + 255) / 256, 256>>>(hist, BH / 2);

    // ---- encoder MLP ----
    {
        GemmP p;
        p = { x16,   w1h, b1, act0h, 2048 };
        hgemm<true><<<dim3(16, 64), 128, SMEM_TOT>>>(p, p, 99, FPPAD, FPPAD);
        p = { act0h, w2h, b2, act1h, 1024 };
        hgemm<true><<<dim3(8,  64), 128, SMEM_TOT>>>(p, p, 99, 2048, 2048);
        p = { act1h, w3h, b3, act0h, 512 };
        hgemm<true><<<dim3(4,  64), 128, SMEM_TOT>>>(p, p, 99, 1024, 1024);
        p = { act0h, w4h, b4, e, 256 };
        hgemm<true><<<dim3(2,  64), 128, SMEM_TOT>>>(p, p, 99, 512, 512);
    }

    // ---- GRU over T steps: 2 fused layer kernels per step ----
    for (int t = 0; t < TSTEPS; t++) {
        const __half* x0   = (t == 0) ? e : (hist + (size_t)t * BH);
        __half* h0prev = (t & 1) ? h0b : h0a;
        __half* h0new  = (t & 1) ? h0a : h0b;
        const __half* h1prev = hist + (size_t)t * BH;
        __half*       h1new  = hist + (size_t)(t + 1) * BH;

        gru_layer<<<dim3(4, 64), 512, L_SMEM>>>(x0,    h0prev, wv0, bv0, h0new);
        gru_layer<<<dim3(4, 64), 512, L_SMEM>>>(h0new, h1prev, wv1, bv1, h1new);
    }

    // ---- fused FC + ReLU + softmax ----
    const long long totalWarps = (long long)BATCH * TSTEPS;
    const int fcBlocks = (int)((totalWarps * 32 + 255) / 256);
    fc_softmax_kernel<<<fcBlocks, 256>>>(hist, wfc, bfc, out);
}